// round 2
// baseline (speedup 1.0000x reference)
#include <cuda_runtime.h>

// ---------------- problem constants ----------------
#define N_EMB   50000
#define B_Q     512
#define E_DIM   16
#define K_NN    20
#define NCHUNK  96
#define CHUNK   521           // 96*521 = 50016 >= 50000
#define NPART   8
#define CPP     (NCHUNK / NPART)   // 12 chunks per merge-part
#define TILE    256
#define QPB     128           // queries per block (threads per block in knn kernel)
#define FLT_BIG 3.402823466e+38f
#define FULLMASK 0xffffffffu
#define BUF_CAP 16

// ---------------- scratch (__device__ globals; no allocation allowed) ----------------
__device__ float g_norm[2 * N_EMB];
__device__ float g_s [2 * B_Q * NCHUNK * K_NN];
__device__ int   g_i [2 * B_Q * NCHUNK * K_NN];
__device__ float g_s2[2 * B_Q * NPART * K_NN];
__device__ int   g_i2[2 * B_Q * NPART * K_NN];
__device__ float g_feats[B_Q * 8];

// ---------------- max-heap of 20 (smallest-20 tracker) ----------------
__device__ __forceinline__ void heap_replace(float* hv, int* hi, float s, int j) {
    int p = 0;
    #pragma unroll
    for (int it = 0; it < 5; it++) {
        int l = 2 * p + 1, r = 2 * p + 2;
        int c = p; float cv = s;
        if (l < K_NN && hv[l] > cv) { c = l; cv = hv[l]; }
        if (r < K_NN && hv[r] > cv) { c = r; cv = hv[r]; }
        if (c == p) break;
        hv[p] = hv[c]; hi[p] = hi[c];
        p = c;
    }
    hv[p] = s; hi[p] = j;
}

// ---------------- kernel 0: candidate half-squared-norms ----------------
__global__ void norm_kernel(const float* __restrict__ emb0, const float* __restrict__ emb1) {
    int t = blockIdx.x * blockDim.x + threadIdx.x;
    if (t >= 2 * N_EMB) return;
    const float* emb = (t < N_EMB) ? emb0 : emb1;
    int j = (t < N_EMB) ? t : (t - N_EMB);
    const float4* e = reinterpret_cast<const float4*>(emb) + (size_t)j * 4;
    float4 v0 = e[0], v1 = e[1], v2 = e[2], v3 = e[3];
    float s = v0.x*v0.x + v0.y*v0.y + v0.z*v0.z + v0.w*v0.w
            + v1.x*v1.x + v1.y*v1.y + v1.z*v1.z + v1.w*v1.w
            + v2.x*v2.x + v2.y*v2.y + v2.z*v2.z + v2.w*v2.w
            + v3.x*v3.x + v3.y*v3.y + v3.z*v3.z + v3.w*v3.w;
    g_norm[t] = 0.5f * s;
}

// ---------------- kernel 1: per-(pass, query, chunk) top-20 by s = 0.5|e|^2 - a.e ----------------
__global__ __launch_bounds__(QPB) void knn_topk_kernel(
    const float* __restrict__ emb0, const float* __restrict__ emb1,
    const int* __restrict__ idx0, const int* __restrict__ idx1)
{
    const int chunk = blockIdx.x;
    const int qg    = blockIdx.y;
    const int pass  = blockIdx.z;

    const float* emb   = pass ? emb1 : emb0;
    const int*   idxA  = pass ? idx1 : idx0;
    const float* normv = g_norm + pass * N_EMB;

    const int q    = qg * QPB + threadIdx.x;
    const int self = idxA[q];

    float a[E_DIM];
    {
        const float4* av = reinterpret_cast<const float4*>(emb) + (size_t)self * 4;
        float4 a0 = av[0], a1 = av[1], a2 = av[2], a3 = av[3];
        a[0]=a0.x; a[1]=a0.y; a[2]=a0.z; a[3]=a0.w;
        a[4]=a1.x; a[5]=a1.y; a[6]=a1.z; a[7]=a1.w;
        a[8]=a2.x; a[9]=a2.y; a[10]=a2.z; a[11]=a2.w;
        a[12]=a3.x; a[13]=a3.y; a[14]=a3.z; a[15]=a3.w;
    }

    float hv[K_NN]; int hi[K_NN];
    #pragma unroll
    for (int k = 0; k < K_NN; k++) { hv[k] = FLT_BIG; hi[k] = 0; }
    float tau = FLT_BIG;
    float bs_[BUF_CAP]; int bj_[BUF_CAP]; int bcnt = 0;

    __shared__ float4 smE[TILE * 4];
    __shared__ float  smN[TILE];

    const int c0 = chunk * CHUNK;
    const int c1 = min(c0 + CHUNK, N_EMB);

    for (int base = c0; base < c1; base += TILE) {
        const int nc  = min(TILE, c1 - base);
        const int ncp = (nc + 1) & ~1;
        __syncthreads();
        {
            const float4* gE = reinterpret_cast<const float4*>(emb) + (size_t)base * 4;
            for (int i = threadIdx.x; i < nc * 4; i += QPB) smE[i] = gE[i];
            for (int i = threadIdx.x; i < nc; i += QPB)     smN[i] = normv[base + i];
            if (ncp > nc) {
                if (threadIdx.x < 4) smE[nc * 4 + threadIdx.x] = make_float4(0.f, 0.f, 0.f, 0.f);
                if (threadIdx.x == 0) smN[nc] = FLT_BIG;
            }
        }
        __syncthreads();

        for (int cc = 0; cc < ncp; cc += 2) {
            const int j0 = base + cc, j1 = j0 + 1;
            float4 e0 = smE[4*cc+0], e1 = smE[4*cc+1], e2 = smE[4*cc+2], e3 = smE[4*cc+3];
            float4 f0 = smE[4*cc+4], f1v = smE[4*cc+5], f2v = smE[4*cc+6], f3v = smE[4*cc+7];

            float p0 = e0.x * a[0];
            float p1 = e0.y * a[1];
            p0 = fmaf(e0.z, a[2],  p0); p1 = fmaf(e0.w, a[3],  p1);
            p0 = fmaf(e1.x, a[4],  p0); p1 = fmaf(e1.y, a[5],  p1);
            p0 = fmaf(e1.z, a[6],  p0); p1 = fmaf(e1.w, a[7],  p1);
            p0 = fmaf(e2.x, a[8],  p0); p1 = fmaf(e2.y, a[9],  p1);
            p0 = fmaf(e2.z, a[10], p0); p1 = fmaf(e2.w, a[11], p1);
            p0 = fmaf(e3.x, a[12], p0); p1 = fmaf(e3.y, a[13], p1);
            p0 = fmaf(e3.z, a[14], p0); p1 = fmaf(e3.w, a[15], p1);

            float q0 = f0.x * a[0];
            float q1 = f0.y * a[1];
            q0 = fmaf(f0.z,  a[2],  q0); q1 = fmaf(f0.w,  a[3],  q1);
            q0 = fmaf(f1v.x, a[4],  q0); q1 = fmaf(f1v.y, a[5],  q1);
            q0 = fmaf(f1v.z, a[6],  q0); q1 = fmaf(f1v.w, a[7],  q1);
            q0 = fmaf(f2v.x, a[8],  q0); q1 = fmaf(f2v.y, a[9],  q1);
            q0 = fmaf(f2v.z, a[10], q0); q1 = fmaf(f2v.w, a[11], q1);
            q0 = fmaf(f3v.x, a[12], q0); q1 = fmaf(f3v.y, a[13], q1);
            q0 = fmaf(f3v.z, a[14], q0); q1 = fmaf(f3v.w, a[15], q1);

            float s0 = smN[cc]     - (p0 + p1);
            float s1 = smN[cc + 1] - (q0 + q1);

            bool push0 = (s0 < tau) && (j0 != self);
            bool push1 = (s1 < tau) && (j1 != self);
            if (push0) { bs_[bcnt] = s0; bj_[bcnt] = j0; bcnt++; }
            if (push1) { bs_[bcnt] = s1; bj_[bcnt] = j1; bcnt++; }

            if (__any_sync(FULLMASK, bcnt >= BUF_CAP - 2)) {
                if (bcnt) {
                    for (int k = 0; k < bcnt; k++) {
                        float fs = bs_[k];
                        if (fs < hv[0]) heap_replace(hv, hi, fs, bj_[k]);
                    }
                    bcnt = 0;
                }
                tau = hv[0];
            }
        }
    }

    if (bcnt) {
        for (int k = 0; k < bcnt; k++) {
            float fs = bs_[k];
            if (fs < hv[0]) heap_replace(hv, hi, fs, bj_[k]);
        }
    }

    const size_t o = ((size_t)(pass * B_Q + q) * NCHUNK + chunk) * K_NN;
    #pragma unroll
    for (int k = 0; k < K_NN; k++) { g_s[o + k] = hv[k]; g_i[o + k] = hi[k]; }
}

// ---------------- kernel 2a: merge 12 chunk-lists -> top-20 per part ----------------
__global__ void merge1_kernel() {
    int t = blockIdx.x * blockDim.x + threadIdx.x;
    if (t >= 2 * B_Q * NPART) return;
    const int part = t & (NPART - 1);
    const int pq   = t >> 3;   // pass*B_Q + q

    float hv[K_NN]; int hi[K_NN];
    #pragma unroll
    for (int k = 0; k < K_NN; k++) { hv[k] = FLT_BIG; hi[k] = 0; }
    float tau = FLT_BIG;

    const size_t off = ((size_t)pq * NCHUNK + (size_t)part * CPP) * K_NN;
    const float* S = g_s + off;
    const int*   I = g_i + off;
    #pragma unroll 4
    for (int k = 0; k < CPP * K_NN; k++) {
        float s = S[k];
        if (s < tau) { heap_replace(hv, hi, s, I[k]); tau = hv[0]; }
    }

    const size_t o2 = (size_t)t * K_NN;
    #pragma unroll
    for (int k = 0; k < K_NN; k++) { g_s2[o2 + k] = hv[k]; g_i2[o2 + k] = hi[k]; }
}

// ---------------- kernel 2b: final merge + features ----------------
__global__ void merge2_kernel(
    const float* __restrict__ emb0, const float* __restrict__ emb1,
    const float* __restrict__ rctx0, const float* __restrict__ rctx1,
    const int* __restrict__ idx0, const int* __restrict__ idx1,
    const float* __restrict__ mean_in, const float* __restrict__ std_in)
{
    int t = blockIdx.x * blockDim.x + threadIdx.x;
    if (t >= 2 * B_Q) return;
    const int pass = t >> 9;
    const int q    = t & (B_Q - 1);

    const float* rctx = pass ? rctx1 : rctx0;
    const float* emb  = pass ? emb1 : emb0;
    const int self = (pass ? idx1 : idx0)[q];

    float na;
    {
        const float4* av = reinterpret_cast<const float4*>(emb) + (size_t)self * 4;
        float4 a0 = av[0], a1 = av[1], a2 = av[2], a3 = av[3];
        na = a0.x*a0.x + a0.y*a0.y + a0.z*a0.z + a0.w*a0.w
           + a1.x*a1.x + a1.y*a1.y + a1.z*a1.z + a1.w*a1.w
           + a2.x*a2.x + a2.y*a2.y + a2.z*a2.z + a2.w*a2.w
           + a3.x*a3.x + a3.y*a3.y + a3.z*a3.z + a3.w*a3.w;
    }

    float hv[K_NN]; int hi[K_NN];
    #pragma unroll
    for (int k = 0; k < K_NN; k++) { hv[k] = FLT_BIG; hi[k] = 0; }
    float tau = FLT_BIG;

    const float* S = g_s2 + (size_t)t * (NPART * K_NN);
    const int*   I = g_i2 + (size_t)t * (NPART * K_NN);
    #pragma unroll 4
    for (int k = 0; k < NPART * K_NN; k++) {
        float s = S[k];
        if (s < tau) { heap_replace(hv, hi, s, I[k]); tau = hv[0]; }
    }

    float ys[K_NN];
    float f1 = 0.f, f2n = 0.f, ysum = 0.f;
    #pragma unroll
    for (int k = 0; k < K_NN; k++) {
        // s = 0.5|e|^2 - a.e  =>  d^2 = 2s + |a|^2
        float d2 = fmaxf(fmaf(2.f, hv[k], na), 0.f);
        float w  = expf(-(sqrtf(d2) + 0.001f));
        float y  = rctx[(size_t)q * N_EMB + hi[k]];
        f1  += w;
        f2n += y * w;
        ysum += y;
        ys[k] = y;
    }
    float mean = ysum * (1.0f / K_NN);
    float var = 0.f;
    #pragma unroll
    for (int k = 0; k < K_NN; k++) {
        float d = ys[k] - mean;
        var = fmaf(d, d, var);
    }
    float f3 = sqrtf(var * (1.0f / (K_NN - 1)));

    g_feats[q * 8 + pass]     = f1;
    g_feats[q * 8 + 2 + pass] = f2n / f1;
    g_feats[q * 8 + 4 + pass] = f3;
    if (pass == 0) {
        g_feats[q * 8 + 6] = mean_in[q];
        g_feats[q * 8 + 7] = std_in[q];
    }
}

// ---------------- kernel 3: tiny MLP (8 -> 64 -> {mean, std}) ----------------
__global__ void mlp_kernel(
    const float* __restrict__ W1, const float* __restrict__ b1,
    const float* __restrict__ Wm, const float* __restrict__ bm,
    const float* __restrict__ Ws, const float* __restrict__ bs,
    float* __restrict__ out)
{
    __shared__ float sW1[8 * 64];
    __shared__ float sb1[64], sWm[64], sWs[64];
    int tid = threadIdx.x;
    for (int i = tid; i < 512; i += blockDim.x) sW1[i] = W1[i];
    if (tid < 64) { sb1[tid] = b1[tid]; sWm[tid] = Wm[tid]; sWs[tid] = Ws[tid]; }
    __syncthreads();

    int q = blockIdx.x * blockDim.x + tid;
    if (q >= B_Q) return;

    float f[8];
    #pragma unroll
    for (int i = 0; i < 8; i++) f[i] = g_feats[q * 8 + i];

    float m = 0.f, sd = 0.f;
    #pragma unroll 8
    for (int j = 0; j < 64; j++) {
        float acc = sb1[j];
        #pragma unroll
        for (int i = 0; i < 8; i++) acc = fmaf(f[i], sW1[i * 64 + j], acc);
        float h = fmaxf(acc, 0.f);
        m  = fmaf(h, sWm[j], m);
        sd = fmaf(h, sWs[j], sd);
    }
    out[q]        = m  + bm[0];
    out[B_Q + q]  = sd + bs[0];
}

// ---------------- launcher ----------------
extern "C" void kernel_launch(void* const* d_in, const int* in_sizes, int n_in,
                              void* d_out, int out_size)
{
    const float* emb0    = (const float*)d_in[0];
    const float* emb1    = (const float*)d_in[1];
    const float* rctx0   = (const float*)d_in[2];
    const float* rctx1   = (const float*)d_in[3];
    const int*   idx0    = (const int*)d_in[4];
    const int*   idx1    = (const int*)d_in[5];
    const float* mean_in = (const float*)d_in[6];
    const float* std_in  = (const float*)d_in[7];
    const float* W1      = (const float*)d_in[8];
    const float* b1      = (const float*)d_in[9];
    const float* Wm      = (const float*)d_in[10];
    const float* bm      = (const float*)d_in[11];
    const float* Ws      = (const float*)d_in[12];
    const float* bs      = (const float*)d_in[13];
    float* out = (float*)d_out;

    norm_kernel<<<(2 * N_EMB + 255) / 256, 256>>>(emb0, emb1);

    dim3 g1(NCHUNK, B_Q / QPB, 2);
    knn_topk_kernel<<<g1, QPB>>>(emb0, emb1, idx0, idx1);

    merge1_kernel<<<(2 * B_Q * NPART + 127) / 128, 128>>>();

    merge2_kernel<<<(2 * B_Q + 127) / 128, 128>>>(emb0, emb1, rctx0, rctx1,
                                                  idx0, idx1, mean_in, std_in);

    mlp_kernel<<<2, 256>>>(W1, b1, Wm, bm, Ws, bs, out);
}

// round 3
// speedup vs baseline: 2.4546x; 2.4546x over previous
#include <cuda_runtime.h>

// ---------------- problem constants ----------------
#define N_EMB   50000
#define B_Q     512
#define E_DIM   16
#define K_NN    20
#define NCHUNK  64
#define CHUNK   782           // 64*782 = 50048 >= 50000
#define TILE    256
#define QPB     128
#define FLT_BIG 3.402823466e+38f
#define FULLMASK 0xffffffffu
#define BUF_CAP 16

// ---------------- scratch ----------------
__device__ float g_norm[2 * N_EMB];
__device__ float g_s [2 * B_Q * NCHUNK * K_NN];
__device__ int   g_i [2 * B_Q * NCHUNK * K_NN];
__device__ float g_feats[B_Q * 8];

// ---------------- branch-free sorted insert into 20 registers ----------------
// rv ascending; caller gates with (s < rv[19]). Evicts current max.
__device__ __forceinline__ void sins(float (&rv)[K_NN], int (&ri)[K_NN], float s, int j) {
    float cv = s; int ci = j;
    #pragma unroll
    for (int k = 0; k < K_NN; k++) {
        bool sm = cv < rv[k];
        float tv = rv[k]; int ti = ri[k];
        rv[k] = sm ? cv : rv[k];
        ri[k] = sm ? ci : ri[k];
        cv = sm ? tv : cv;
        ci = sm ? ti : ci;
    }
}

// ---------------- kernel 0: half squared norms ----------------
__global__ void norm_kernel(const float* __restrict__ emb0, const float* __restrict__ emb1) {
    int t = blockIdx.x * blockDim.x + threadIdx.x;
    if (t >= 2 * N_EMB) return;
    const float* emb = (t < N_EMB) ? emb0 : emb1;
    int j = (t < N_EMB) ? t : (t - N_EMB);
    const float4* e = reinterpret_cast<const float4*>(emb) + (size_t)j * 4;
    float4 v0 = e[0], v1 = e[1], v2 = e[2], v3 = e[3];
    float s = v0.x*v0.x + v0.y*v0.y + v0.z*v0.z + v0.w*v0.w
            + v1.x*v1.x + v1.y*v1.y + v1.z*v1.z + v1.w*v1.w
            + v2.x*v2.x + v2.y*v2.y + v2.z*v2.z + v2.w*v2.w
            + v3.x*v3.x + v3.y*v3.y + v3.z*v3.z + v3.w*v3.w;
    g_norm[t] = 0.5f * s;
}

// ---------------- kernel 1: per-(pass,query,chunk) top-20 ----------------
__global__ __launch_bounds__(QPB) void knn_topk_kernel(
    const float* __restrict__ emb0, const float* __restrict__ emb1,
    const int* __restrict__ idx0, const int* __restrict__ idx1)
{
    const int chunk = blockIdx.x;
    const int qg    = blockIdx.y;
    const int pass  = blockIdx.z;

    const float* emb   = pass ? emb1 : emb0;
    const int*   idxA  = pass ? idx1 : idx0;
    const float* normv = g_norm + pass * N_EMB;

    const int q    = qg * QPB + threadIdx.x;
    const int self = idxA[q];

    float a[E_DIM];
    {
        const float4* av = reinterpret_cast<const float4*>(emb) + (size_t)self * 4;
        float4 a0 = av[0], a1 = av[1], a2 = av[2], a3 = av[3];
        a[0]=a0.x; a[1]=a0.y; a[2]=a0.z; a[3]=a0.w;
        a[4]=a1.x; a[5]=a1.y; a[6]=a1.z; a[7]=a1.w;
        a[8]=a2.x; a[9]=a2.y; a[10]=a2.z; a[11]=a2.w;
        a[12]=a3.x; a[13]=a3.y; a[14]=a3.z; a[15]=a3.w;
    }

    float rv[K_NN]; int ri[K_NN];
    #pragma unroll
    for (int k = 0; k < K_NN; k++) { rv[k] = FLT_BIG; ri[k] = 0; }
    float tau = FLT_BIG;
    float bs_[BUF_CAP]; int bj_[BUF_CAP]; int bcnt = 0;

    __shared__ float4 smE[TILE * 4];
    __shared__ float  smN[TILE];

    const int c0 = chunk * CHUNK;
    const int c1 = min(c0 + CHUNK, N_EMB);

    for (int base = c0; base < c1; base += TILE) {
        const int nc  = min(TILE, c1 - base);
        const int ncp = (nc + 1) & ~1;
        __syncthreads();
        {
            const float4* gE = reinterpret_cast<const float4*>(emb) + (size_t)base * 4;
            for (int i = threadIdx.x; i < nc * 4; i += QPB) smE[i] = gE[i];
            for (int i = threadIdx.x; i < nc; i += QPB)     smN[i] = normv[base + i];
            if (ncp > nc) {
                if (threadIdx.x < 4) smE[nc * 4 + threadIdx.x] = make_float4(0.f, 0.f, 0.f, 0.f);
                if (threadIdx.x == 0) smN[nc] = FLT_BIG;
            }
        }
        __syncthreads();

        for (int cc = 0; cc < ncp; cc += 2) {
            const int j0 = base + cc, j1 = j0 + 1;
            float4 e0 = smE[4*cc+0], e1 = smE[4*cc+1], e2 = smE[4*cc+2], e3 = smE[4*cc+3];
            float4 f0 = smE[4*cc+4], f1v = smE[4*cc+5], f2v = smE[4*cc+6], f3v = smE[4*cc+7];

            float p0 = e0.x * a[0];
            float p1 = e0.y * a[1];
            p0 = fmaf(e0.z, a[2],  p0); p1 = fmaf(e0.w, a[3],  p1);
            p0 = fmaf(e1.x, a[4],  p0); p1 = fmaf(e1.y, a[5],  p1);
            p0 = fmaf(e1.z, a[6],  p0); p1 = fmaf(e1.w, a[7],  p1);
            p0 = fmaf(e2.x, a[8],  p0); p1 = fmaf(e2.y, a[9],  p1);
            p0 = fmaf(e2.z, a[10], p0); p1 = fmaf(e2.w, a[11], p1);
            p0 = fmaf(e3.x, a[12], p0); p1 = fmaf(e3.y, a[13], p1);
            p0 = fmaf(e3.z, a[14], p0); p1 = fmaf(e3.w, a[15], p1);

            float q0 = f0.x * a[0];
            float q1 = f0.y * a[1];
            q0 = fmaf(f0.z,  a[2],  q0); q1 = fmaf(f0.w,  a[3],  q1);
            q0 = fmaf(f1v.x, a[4],  q0); q1 = fmaf(f1v.y, a[5],  q1);
            q0 = fmaf(f1v.z, a[6],  q0); q1 = fmaf(f1v.w, a[7],  q1);
            q0 = fmaf(f2v.x, a[8],  q0); q1 = fmaf(f2v.y, a[9],  q1);
            q0 = fmaf(f2v.z, a[10], q0); q1 = fmaf(f2v.w, a[11], q1);
            q0 = fmaf(f3v.x, a[12], q0); q1 = fmaf(f3v.y, a[13], q1);
            q0 = fmaf(f3v.z, a[14], q0); q1 = fmaf(f3v.w, a[15], q1);

            float s0 = smN[cc]     - (p0 + p1);
            float s1 = smN[cc + 1] - (q0 + q1);

            bool push0 = (s0 < tau) && (j0 != self);
            bool push1 = (s1 < tau) && (j1 != self);
            if (push0) { bs_[bcnt] = s0; bj_[bcnt] = j0; bcnt++; }
            if (push1) { bs_[bcnt] = s1; bj_[bcnt] = j1; bcnt++; }

            if (__any_sync(FULLMASK, bcnt >= BUF_CAP - 2)) {
                for (int k = 0; k < bcnt; k++) {
                    float fs = bs_[k];
                    if (fs < rv[K_NN - 1]) sins(rv, ri, fs, bj_[k]);
                }
                bcnt = 0;
                tau = rv[K_NN - 1];
            }
        }
    }

    for (int k = 0; k < bcnt; k++) {
        float fs = bs_[k];
        if (fs < rv[K_NN - 1]) sins(rv, ri, fs, bj_[k]);
    }

    // sorted ascending output
    const size_t o = ((size_t)(pass * B_Q + q) * NCHUNK + chunk) * K_NN;
    #pragma unroll
    for (int k = 0; k < K_NN; k++) { g_s[o + k] = rv[k]; g_i[o + k] = ri[k]; }
}

// ---------------- kernel 2: final merge (sorted lists, early exit) + features ----------------
__global__ __launch_bounds__(32) void merge_kernel(
    const float* __restrict__ emb0, const float* __restrict__ emb1,
    const float* __restrict__ rctx0, const float* __restrict__ rctx1,
    const int* __restrict__ idx0, const int* __restrict__ idx1,
    const float* __restrict__ mean_in, const float* __restrict__ std_in)
{
    int t = blockIdx.x * blockDim.x + threadIdx.x;
    if (t >= 2 * B_Q) return;
    const int pass = t >> 9;
    const int q    = t & (B_Q - 1);

    const float* rctx = pass ? rctx1 : rctx0;
    const float* emb  = pass ? emb1 : emb0;
    const int self = (pass ? idx1 : idx0)[q];

    float na;
    {
        const float4* av = reinterpret_cast<const float4*>(emb) + (size_t)self * 4;
        float4 a0 = av[0], a1 = av[1], a2 = av[2], a3 = av[3];
        na = a0.x*a0.x + a0.y*a0.y + a0.z*a0.z + a0.w*a0.w
           + a1.x*a1.x + a1.y*a1.y + a1.z*a1.z + a1.w*a1.w
           + a2.x*a2.x + a2.y*a2.y + a2.z*a2.z + a2.w*a2.w
           + a3.x*a3.x + a3.y*a3.y + a3.z*a3.z + a3.w*a3.w;
    }

    float rv[K_NN]; int ri[K_NN];
    #pragma unroll
    for (int k = 0; k < K_NN; k++) { rv[k] = FLT_BIG; ri[k] = 0; }

    const float* S = g_s + (size_t)t * (NCHUNK * K_NN);
    const int*   I = g_i + (size_t)t * (NCHUNK * K_NN);
    for (int m = 0; m < NCHUNK; m++) {
        const float* Sm = S + m * K_NN;
        const int*   Im = I + m * K_NN;
        #pragma unroll 4
        for (int k = 0; k < K_NN; k++) {
            float s = Sm[k];
            if (s >= rv[K_NN - 1]) break;   // sorted list -> rest can't qualify
            sins(rv, ri, s, Im[k]);
        }
    }

    float ys[K_NN];
    float f1 = 0.f, f2n = 0.f, ysum = 0.f;
    #pragma unroll
    for (int k = 0; k < K_NN; k++) {
        float d2 = fmaxf(fmaf(2.f, rv[k], na), 0.f);   // d^2 = 2s + |a|^2
        float w  = expf(-(sqrtf(d2) + 0.001f));
        float y  = rctx[(size_t)q * N_EMB + ri[k]];
        f1  += w;
        f2n += y * w;
        ysum += y;
        ys[k] = y;
    }
    float mean = ysum * (1.0f / K_NN);
    float var = 0.f;
    #pragma unroll
    for (int k = 0; k < K_NN; k++) {
        float d = ys[k] - mean;
        var = fmaf(d, d, var);
    }
    float f3 = sqrtf(var * (1.0f / (K_NN - 1)));

    g_feats[q * 8 + pass]     = f1;
    g_feats[q * 8 + 2 + pass] = f2n / f1;
    g_feats[q * 8 + 4 + pass] = f3;
    if (pass == 0) {
        g_feats[q * 8 + 6] = mean_in[q];
        g_feats[q * 8 + 7] = std_in[q];
    }
}

// ---------------- kernel 3: tiny MLP ----------------
__global__ void mlp_kernel(
    const float* __restrict__ W1, const float* __restrict__ b1,
    const float* __restrict__ Wm, const float* __restrict__ bm,
    const float* __restrict__ Ws, const float* __restrict__ bs,
    float* __restrict__ out)
{
    __shared__ float sW1[8 * 64];
    __shared__ float sb1[64], sWm[64], sWs[64];
    int tid = threadIdx.x;
    for (int i = tid; i < 512; i += blockDim.x) sW1[i] = W1[i];
    if (tid < 64) { sb1[tid] = b1[tid]; sWm[tid] = Wm[tid]; sWs[tid] = Ws[tid]; }
    __syncthreads();

    int q = blockIdx.x * blockDim.x + tid;
    if (q >= B_Q) return;

    float f[8];
    #pragma unroll
    for (int i = 0; i < 8; i++) f[i] = g_feats[q * 8 + i];

    float m = 0.f, sd = 0.f;
    #pragma unroll 8
    for (int j = 0; j < 64; j++) {
        float acc = sb1[j];
        #pragma unroll
        for (int i = 0; i < 8; i++) acc = fmaf(f[i], sW1[i * 64 + j], acc);
        float h = fmaxf(acc, 0.f);
        m  = fmaf(h, sWm[j], m);
        sd = fmaf(h, sWs[j], sd);
    }
    out[q]        = m  + bm[0];
    out[B_Q + q]  = sd + bs[0];
}

// ---------------- launcher ----------------
extern "C" void kernel_launch(void* const* d_in, const int* in_sizes, int n_in,
                              void* d_out, int out_size)
{
    const float* emb0    = (const float*)d_in[0];
    const float* emb1    = (const float*)d_in[1];
    const float* rctx0   = (const float*)d_in[2];
    const float* rctx1   = (const float*)d_in[3];
    const int*   idx0    = (const int*)d_in[4];
    const int*   idx1    = (const int*)d_in[5];
    const float* mean_in = (const float*)d_in[6];
    const float* std_in  = (const float*)d_in[7];
    const float* W1      = (const float*)d_in[8];
    const float* b1      = (const float*)d_in[9];
    const float* Wm      = (const float*)d_in[10];
    const float* bm      = (const float*)d_in[11];
    const float* Ws      = (const float*)d_in[12];
    const float* bs      = (const float*)d_in[13];
    float* out = (float*)d_out;

    norm_kernel<<<(2 * N_EMB + 255) / 256, 256>>>(emb0, emb1);

    dim3 g1(NCHUNK, B_Q / QPB, 2);
    knn_topk_kernel<<<g1, QPB>>>(emb0, emb1, idx0, idx1);

    merge_kernel<<<(2 * B_Q + 31) / 32, 32>>>(emb0, emb1, rctx0, rctx1,
                                              idx0, idx1, mean_in, std_in);

    mlp_kernel<<<2, 256>>>(W1, b1, Wm, bm, Ws, bs, out);
}

// round 4
// speedup vs baseline: 3.7332x; 1.5209x over previous
#include <cuda_runtime.h>

// ---------------- problem constants ----------------
#define N_EMB   50000
#define B_Q     512
#define E_DIM   16
#define K_NN    20
#define NCHUNK  64
#define CHUNK   782           // 64*782 = 50048 >= 50000
#define TILE    256
#define QPB     128
#define CAP     1024          // survivor buffer per (pass,query)
#define SSTRIDE 48            // sample stride: 1024*48 = 49152 < 50000
#define FLT_BIG 3.402823466e+38f
#define FULLMASK 0xffffffffu
#define NORMB   391           // blocks for norm part (391*256 >= 100000)
#define SAMPB   128           // blocks for sample part (128*8 warps = 1024 queries)

// ---------------- scratch ----------------
__device__ float g_norm[2 * N_EMB];
__device__ float g_tau [2 * B_Q];
__device__ int   g_cnt [2 * B_Q];
__device__ float g_fs  [2 * B_Q * CAP];
__device__ int   g_fj  [2 * B_Q * CAP];

// ---------------- branch-free sorted insert (ascending) ----------------
template <int S>
__device__ __forceinline__ void sinsN(float (&rv)[S], int (&ri)[S], float s, int j) {
    float cv = s; int ci = j;
    #pragma unroll
    for (int k = 0; k < S; k++) {
        bool sm = cv < rv[k];
        float tv = rv[k]; int ti = ri[k];
        rv[k] = sm ? cv : rv[k];
        ri[k] = sm ? ci : ri[k];
        cv = sm ? tv : cv;
        ci = sm ? ti : ci;
    }
}

template <int S>
__device__ __forceinline__ void popN(float (&rv)[S], int (&ri)[S]) {
    #pragma unroll
    for (int k = 0; k < S - 1; k++) { rv[k] = rv[k + 1]; ri[k] = ri[k + 1]; }
    rv[S - 1] = FLT_BIG; ri[S - 1] = 0;
}

// warp-wide min with payload (id) and origin lane
__device__ __forceinline__ void wmin(float& v, int& id, int& ln) {
    #pragma unroll
    for (int off = 16; off; off >>= 1) {
        float ov = __shfl_xor_sync(FULLMASK, v,  off);
        int  oid = __shfl_xor_sync(FULLMASK, id, off);
        int  oln = __shfl_xor_sync(FULLMASK, ln, off);
        if (ov < v) { v = ov; id = oid; ln = oln; }
    }
}

__device__ __forceinline__ float dot16(const float4* __restrict__ e, const float a[E_DIM]) {
    float4 v0 = e[0], v1 = e[1], v2 = e[2], v3 = e[3];
    float p0 = v0.x * a[0];
    float p1 = v0.y * a[1];
    p0 = fmaf(v0.z, a[2],  p0); p1 = fmaf(v0.w, a[3],  p1);
    p0 = fmaf(v1.x, a[4],  p0); p1 = fmaf(v1.y, a[5],  p1);
    p0 = fmaf(v1.z, a[6],  p0); p1 = fmaf(v1.w, a[7],  p1);
    p0 = fmaf(v2.x, a[8],  p0); p1 = fmaf(v2.y, a[9],  p1);
    p0 = fmaf(v2.z, a[10], p0); p1 = fmaf(v2.w, a[11], p1);
    p0 = fmaf(v3.x, a[12], p0); p1 = fmaf(v3.y, a[13], p1);
    p0 = fmaf(v3.z, a[14], p0); p1 = fmaf(v3.w, a[15], p1);
    return p0 + p1;
}

// ============ kernel A: norms (blocks [0,NORMB)) + per-query tau (blocks [NORMB, NORMB+SAMPB)) ============
__global__ __launch_bounds__(256) void prep_kernel(
    const float* __restrict__ emb0, const float* __restrict__ emb1,
    const int* __restrict__ idx0, const int* __restrict__ idx1)
{
    const int b = blockIdx.x;
    if (b < NORMB) {
        int t = b * 256 + threadIdx.x;
        if (t >= 2 * N_EMB) return;
        const float* emb = (t < N_EMB) ? emb0 : emb1;
        int j = (t < N_EMB) ? t : (t - N_EMB);
        const float4* e = reinterpret_cast<const float4*>(emb) + (size_t)j * 4;
        float4 v0 = e[0], v1 = e[1], v2 = e[2], v3 = e[3];
        float s = v0.x*v0.x + v0.y*v0.y + v0.z*v0.z + v0.w*v0.w
                + v1.x*v1.x + v1.y*v1.y + v1.z*v1.z + v1.w*v1.w
                + v2.x*v2.x + v2.y*v2.y + v2.z*v2.z + v2.w*v2.w
                + v3.x*v3.x + v3.y*v3.y + v3.z*v3.z + v3.w*v3.w;
        g_norm[t] = 0.5f * s;
        return;
    }

    // ---- sample/tau part: one warp per (pass, query) ----
    const int sb   = b - NORMB;
    const int wid  = threadIdx.x >> 5;
    const int lane = threadIdx.x & 31;
    const int w    = sb * 8 + wid;          // [0, 1024)
    const int pass = w >> 9;
    const int q    = w & (B_Q - 1);

    const float* emb  = pass ? emb1 : emb0;
    const int    self = (pass ? idx1 : idx0)[q];
    const float4* emb4 = reinterpret_cast<const float4*>(emb);

    float a[E_DIM];
    {
        const float4* av = emb4 + (size_t)self * 4;
        float4 a0 = av[0], a1 = av[1], a2 = av[2], a3 = av[3];
        a[0]=a0.x; a[1]=a0.y; a[2]=a0.z; a[3]=a0.w;
        a[4]=a1.x; a[5]=a1.y; a[6]=a1.z; a[7]=a1.w;
        a[8]=a2.x; a[9]=a2.y; a[10]=a2.z; a[11]=a2.w;
        a[12]=a3.x; a[13]=a3.y; a[14]=a3.z; a[15]=a3.w;
    }

    float rv[8]; int ri[8];
    #pragma unroll
    for (int k = 0; k < 8; k++) { rv[k] = FLT_BIG; ri[k] = 0; }

    #pragma unroll 4
    for (int i = 0; i < 32; i++) {
        int si = i * 32 + lane;
        int j  = si * SSTRIDE;
        if (j == self) continue;
        const float4* e = emb4 + (size_t)j * 4;
        float4 v0 = e[0], v1 = e[1], v2 = e[2], v3 = e[3];
        float nrm = v0.x*v0.x + v0.y*v0.y + v0.z*v0.z + v0.w*v0.w
                  + v1.x*v1.x + v1.y*v1.y + v1.z*v1.z + v1.w*v1.w
                  + v2.x*v2.x + v2.y*v2.y + v2.z*v2.z + v2.w*v2.w
                  + v3.x*v3.x + v3.y*v3.y + v3.z*v3.z + v3.w*v3.w;
        float p0 = v0.x * a[0];
        float p1 = v0.y * a[1];
        p0 = fmaf(v0.z, a[2],  p0); p1 = fmaf(v0.w, a[3],  p1);
        p0 = fmaf(v1.x, a[4],  p0); p1 = fmaf(v1.y, a[5],  p1);
        p0 = fmaf(v1.z, a[6],  p0); p1 = fmaf(v1.w, a[7],  p1);
        p0 = fmaf(v2.x, a[8],  p0); p1 = fmaf(v2.y, a[9],  p1);
        p0 = fmaf(v2.z, a[10], p0); p1 = fmaf(v2.w, a[11], p1);
        p0 = fmaf(v3.x, a[12], p0); p1 = fmaf(v3.y, a[13], p1);
        p0 = fmaf(v3.z, a[14], p0); p1 = fmaf(v3.w, a[15], p1);
        float s = 0.5f * nrm - (p0 + p1);
        if (s < rv[7]) sinsN<8>(rv, ri, s, j);
    }

    // extract 8 smallest warp-wide; tau = 8th
    float tau = 0.f;
    #pragma unroll
    for (int r = 0; r < 8; r++) {
        float v = rv[0]; int id = ri[0]; int ln = lane;
        wmin(v, id, ln);
        if (lane == ln) popN<8>(rv, ri);
        tau = v;
    }

    if (lane == 0) { g_tau[w] = tau; g_cnt[w] = 0; }
}

// ============ kernel B: filter all candidates against tau ============
__global__ __launch_bounds__(QPB) void filter_kernel(
    const float* __restrict__ emb0, const float* __restrict__ emb1,
    const int* __restrict__ idx0, const int* __restrict__ idx1)
{
    const int chunk = blockIdx.x;
    const int qg    = blockIdx.y;
    const int pass  = blockIdx.z;

    const float* emb   = pass ? emb1 : emb0;
    const float* normv = g_norm + pass * N_EMB;

    const int q    = qg * QPB + threadIdx.x;
    const int t2   = pass * B_Q + q;
    const int self = (pass ? idx1 : idx0)[q];
    const float tau = g_tau[t2];

    float a[E_DIM];
    {
        const float4* av = reinterpret_cast<const float4*>(emb) + (size_t)self * 4;
        float4 a0 = av[0], a1 = av[1], a2 = av[2], a3 = av[3];
        a[0]=a0.x; a[1]=a0.y; a[2]=a0.z; a[3]=a0.w;
        a[4]=a1.x; a[5]=a1.y; a[6]=a1.z; a[7]=a1.w;
        a[8]=a2.x; a[9]=a2.y; a[10]=a2.z; a[11]=a2.w;
        a[12]=a3.x; a[13]=a3.y; a[14]=a3.z; a[15]=a3.w;
    }

    __shared__ float4 smE[TILE * 4];
    __shared__ float  smN[TILE];

    const int c0 = chunk * CHUNK;
    const int c1 = min(c0 + CHUNK, N_EMB);

    for (int base = c0; base < c1; base += TILE) {
        const int nc  = min(TILE, c1 - base);
        const int ncp = (nc + 1) & ~1;
        __syncthreads();
        {
            const float4* gE = reinterpret_cast<const float4*>(emb) + (size_t)base * 4;
            for (int i = threadIdx.x; i < nc * 4; i += QPB) smE[i] = gE[i];
            for (int i = threadIdx.x; i < nc; i += QPB)     smN[i] = normv[base + i];
            if (ncp > nc) {
                if (threadIdx.x < 4) smE[nc * 4 + threadIdx.x] = make_float4(0.f, 0.f, 0.f, 0.f);
                if (threadIdx.x == 0) smN[nc] = FLT_BIG;
            }
        }
        __syncthreads();

        for (int cc = 0; cc < ncp; cc += 2) {
            const int j0 = base + cc, j1 = j0 + 1;
            float d0 = dot16(&smE[4 * cc],     a);
            float d1 = dot16(&smE[4 * cc + 4], a);
            float s0 = smN[cc]     - d0;
            float s1 = smN[cc + 1] - d1;

            if (s0 <= tau && j0 != self) {
                int slot = atomicAdd(&g_cnt[t2], 1);
                if (slot < CAP) { g_fs[(size_t)t2 * CAP + slot] = s0; g_fj[(size_t)t2 * CAP + slot] = j0; }
            }
            if (s1 <= tau && j1 != self) {
                int slot = atomicAdd(&g_cnt[t2], 1);
                if (slot < CAP) { g_fs[(size_t)t2 * CAP + slot] = s1; g_fj[(size_t)t2 * CAP + slot] = j1; }
            }
        }
    }
}

// ============ kernel C: exact top-20 of survivors + features + fused MLP ============
// block = 128 threads (4 warps) handles 2 queries x 2 passes; grid = 256 blocks.
__global__ __launch_bounds__(128) void select_kernel(
    const float* __restrict__ rctx0, const float* __restrict__ rctx1,
    const int* __restrict__ idx0, const int* __restrict__ idx1,
    const float* __restrict__ mean_in, const float* __restrict__ std_in,
    const float* __restrict__ W1, const float* __restrict__ b1,
    const float* __restrict__ Wm, const float* __restrict__ bm,
    const float* __restrict__ Ws, const float* __restrict__ bs,
    float* __restrict__ out)
{
    __shared__ float sfe[2][8];

    const int wid  = threadIdx.x >> 5;
    const int lane = threadIdx.x & 31;
    const int ql   = wid >> 1;                 // local query 0/1
    const int pass = wid & 1;
    const int q    = blockIdx.x * 2 + ql;
    const int t2   = pass * B_Q + q;

    const float* rctx = pass ? rctx1 : rctx0;
    const int    self = (pass ? idx1 : idx0)[q];
    const float  na   = 2.0f * g_norm[pass * N_EMB + self];   // |a|^2

    int cnt = g_cnt[t2];
    if (cnt > CAP) cnt = CAP;

    // per-lane sorted-10
    float rv[10]; int ri[10];
    #pragma unroll
    for (int k = 0; k < 10; k++) { rv[k] = FLT_BIG; ri[k] = 0; }
    const float* FS = g_fs + (size_t)t2 * CAP;
    const int*   FJ = g_fj + (size_t)t2 * CAP;
    for (int i = lane; i < cnt; i += 32) {
        float s = FS[i];
        if (s < rv[9]) sinsN<10>(rv, ri, s, FJ[i]);
    }

    // 20 extraction rounds -> lane r holds neighbor r
    float ms = 0.f; int mj = 0;
    #pragma unroll
    for (int r = 0; r < K_NN; r++) {
        float v = rv[0]; int id = ri[0]; int ln = lane;
        wmin(v, id, ln);
        if (lane == ln) popN<10>(rv, ri);
        if (lane == r) { ms = v; mj = id; }
    }

    // features
    const bool act = lane < K_NN;
    float w = 0.f, y = 0.f;
    if (act) {
        float d2 = fmaxf(fmaf(2.f, ms, na), 0.f);
        w = expf(-(sqrtf(d2) + 0.001f));
        y = rctx[(size_t)q * N_EMB + mj];
    }
    float f1 = w, f2n = w * y, ysum = y;
    #pragma unroll
    for (int off = 16; off; off >>= 1) {
        f1   += __shfl_xor_sync(FULLMASK, f1,   off);
        f2n  += __shfl_xor_sync(FULLMASK, f2n,  off);
        ysum += __shfl_xor_sync(FULLMASK, ysum, off);
    }
    float mean = ysum * (1.0f / K_NN);
    float d = act ? (y - mean) : 0.f;
    float var = d * d;
    #pragma unroll
    for (int off = 16; off; off >>= 1) var += __shfl_xor_sync(FULLMASK, var, off);
    float f3 = sqrtf(var * (1.0f / (K_NN - 1)));

    if (lane == 0) {
        sfe[ql][pass]     = f1;
        sfe[ql][2 + pass] = f2n / f1;
        sfe[ql][4 + pass] = f3;
        if (pass == 0) {
            sfe[ql][6] = mean_in[q];
            sfe[ql][7] = std_in[q];
        }
    }
    __syncthreads();

    // fused MLP: warp 0 -> query 0, warp 1 -> query 1
    if (wid < 2) {
        const int mq = blockIdx.x * 2 + wid;
        float f[8];
        #pragma unroll
        for (int i = 0; i < 8; i++) f[i] = sfe[wid][i];

        float m = 0.f, sd = 0.f;
        #pragma unroll
        for (int half = 0; half < 2; half++) {
            int j = lane + half * 32;
            float acc = b1[j];
            #pragma unroll
            for (int i = 0; i < 8; i++) acc = fmaf(f[i], W1[i * 64 + j], acc);
            float h = fmaxf(acc, 0.f);
            m  = fmaf(h, Wm[j], m);
            sd = fmaf(h, Ws[j], sd);
        }
        #pragma unroll
        for (int off = 16; off; off >>= 1) {
            m  += __shfl_xor_sync(FULLMASK, m,  off);
            sd += __shfl_xor_sync(FULLMASK, sd, off);
        }
        if (lane == 0) {
            out[mq]       = m  + bm[0];
            out[B_Q + mq] = sd + bs[0];
        }
    }
}

// ---------------- launcher ----------------
extern "C" void kernel_launch(void* const* d_in, const int* in_sizes, int n_in,
                              void* d_out, int out_size)
{
    const float* emb0    = (const float*)d_in[0];
    const float* emb1    = (const float*)d_in[1];
    const float* rctx0   = (const float*)d_in[2];
    const float* rctx1   = (const float*)d_in[3];
    const int*   idx0    = (const int*)d_in[4];
    const int*   idx1    = (const int*)d_in[5];
    const float* mean_in = (const float*)d_in[6];
    const float* std_in  = (const float*)d_in[7];
    const float* W1      = (const float*)d_in[8];
    const float* b1      = (const float*)d_in[9];
    const float* Wm      = (const float*)d_in[10];
    const float* bm      = (const float*)d_in[11];
    const float* Ws      = (const float*)d_in[12];
    const float* bs      = (const float*)d_in[13];
    float* out = (float*)d_out;

    prep_kernel<<<NORMB + SAMPB, 256>>>(emb0, emb1, idx0, idx1);

    dim3 g1(NCHUNK, B_Q / QPB, 2);
    filter_kernel<<<g1, QPB>>>(emb0, emb1, idx0, idx1);

    select_kernel<<<B_Q / 2, 128>>>(rctx0, rctx1, idx0, idx1, mean_in, std_in,
                                    W1, b1, Wm, bm, Ws, bs, out);
}

// round 5
// speedup vs baseline: 3.9777x; 1.0655x over previous
#include <cuda_runtime.h>

// ---------------- problem constants ----------------
#define N_EMB   50000
#define B_Q     512
#define E_DIM   16
#define K_NN    20
#define NCHUNK  64
#define CHUNK   782           // 64*782 = 50048 >= 50000
#define TILE    256
#define QPB     128
#define CAP     1024
#define FLT_BIG 3.402823466e+38f
#define FULLMASK 0xffffffffu

// ---------------- scratch ----------------
__device__ float g_tau [2 * B_Q];
__device__ int   g_cnt [2 * B_Q];
__device__ float g_fs  [2 * B_Q * CAP];
__device__ int   g_fj  [2 * B_Q * CAP];

// ---------------- helpers ----------------
template <int S>
__device__ __forceinline__ void sinsN(float (&rv)[S], int (&ri)[S], float s, int j) {
    float cv = s; int ci = j;
    #pragma unroll
    for (int k = 0; k < S; k++) {
        bool sm = cv < rv[k];
        float tv = rv[k]; int ti = ri[k];
        rv[k] = sm ? cv : rv[k];
        ri[k] = sm ? ci : ri[k];
        cv = sm ? tv : cv;
        ci = sm ? ti : ci;
    }
}

template <int S>
__device__ __forceinline__ void popN(float (&rv)[S], int (&ri)[S]) {
    #pragma unroll
    for (int k = 0; k < S - 1; k++) { rv[k] = rv[k + 1]; ri[k] = ri[k + 1]; }
    rv[S - 1] = FLT_BIG; ri[S - 1] = 0;
}

__device__ __forceinline__ void wmin(float& v, int& id, int& ln) {
    #pragma unroll
    for (int off = 16; off; off >>= 1) {
        float ov = __shfl_xor_sync(FULLMASK, v,  off);
        int  oid = __shfl_xor_sync(FULLMASK, id, off);
        int  oln = __shfl_xor_sync(FULLMASK, ln, off);
        if (ov < v) { v = ov; id = oid; ln = oln; }
    }
}

__device__ __forceinline__ float dot16s(const float4* __restrict__ e, const float a[E_DIM]) {
    float4 v0 = e[0], v1 = e[1], v2 = e[2], v3 = e[3];
    float p0 = v0.x * a[0];
    float p1 = v0.y * a[1];
    p0 = fmaf(v0.z, a[2],  p0); p1 = fmaf(v0.w, a[3],  p1);
    p0 = fmaf(v1.x, a[4],  p0); p1 = fmaf(v1.y, a[5],  p1);
    p0 = fmaf(v1.z, a[6],  p0); p1 = fmaf(v1.w, a[7],  p1);
    p0 = fmaf(v2.x, a[8],  p0); p1 = fmaf(v2.y, a[9],  p1);
    p0 = fmaf(v2.z, a[10], p0); p1 = fmaf(v2.w, a[11], p1);
    p0 = fmaf(v3.x, a[12], p0); p1 = fmaf(v3.y, a[13], p1);
    p0 = fmaf(v3.z, a[14], p0); p1 = fmaf(v3.w, a[15], p1);
    return p0 + p1;
}

__device__ __forceinline__ void load_q(const float4* emb4, int self, float (&a)[E_DIM]) {
    const float4* av = emb4 + (size_t)self * 4;
    float4 a0 = av[0], a1 = av[1], a2 = av[2], a3 = av[3];
    a[0]=a0.x; a[1]=a0.y; a[2]=a0.z; a[3]=a0.w;
    a[4]=a1.x; a[5]=a1.y; a[6]=a1.z; a[7]=a1.w;
    a[8]=a2.x; a[9]=a2.y; a[10]=a2.z; a[11]=a2.w;
    a[12]=a3.x; a[13]=a3.y; a[14]=a3.z; a[15]=a3.w;
}

// ============ kernel A: per-(pass,query) tau from contiguous 1024-sample ============
// one warp per (pass,query); 128 blocks x 256 threads
__global__ __launch_bounds__(256) void prep_kernel(
    const float* __restrict__ emb0, const float* __restrict__ emb1,
    const int* __restrict__ idx0, const int* __restrict__ idx1)
{
    const int wid  = threadIdx.x >> 5;
    const int lane = threadIdx.x & 31;
    const int w    = blockIdx.x * 8 + wid;  // [0, 1024)
    const int pass = w >> 9;
    const int q    = w & (B_Q - 1);

    const float* emb  = pass ? emb1 : emb0;
    const int    self = (pass ? idx1 : idx0)[q];
    const float4* emb4 = reinterpret_cast<const float4*>(emb);

    float a[E_DIM];
    load_q(emb4, self, a);

    float rv[8]; int ri[8];
    #pragma unroll
    for (int k = 0; k < 8; k++) { rv[k] = FLT_BIG; ri[k] = 0; }

    #pragma unroll 4
    for (int i = 0; i < 32; i++) {
        int j = i * 32 + lane;          // contiguous window [0,1024), L1/L2 resident
        const float4* e = emb4 + (size_t)j * 4;
        float4 v0 = e[0], v1 = e[1], v2 = e[2], v3 = e[3];
        float nrm = v0.x*v0.x + v0.y*v0.y + v0.z*v0.z + v0.w*v0.w
                  + v1.x*v1.x + v1.y*v1.y + v1.z*v1.z + v1.w*v1.w
                  + v2.x*v2.x + v2.y*v2.y + v2.z*v2.z + v2.w*v2.w
                  + v3.x*v3.x + v3.y*v3.y + v3.z*v3.z + v3.w*v3.w;
        float p0 = v0.x * a[0];
        float p1 = v0.y * a[1];
        p0 = fmaf(v0.z, a[2],  p0); p1 = fmaf(v0.w, a[3],  p1);
        p0 = fmaf(v1.x, a[4],  p0); p1 = fmaf(v1.y, a[5],  p1);
        p0 = fmaf(v1.z, a[6],  p0); p1 = fmaf(v1.w, a[7],  p1);
        p0 = fmaf(v2.x, a[8],  p0); p1 = fmaf(v2.y, a[9],  p1);
        p0 = fmaf(v2.z, a[10], p0); p1 = fmaf(v2.w, a[11], p1);
        p0 = fmaf(v3.x, a[12], p0); p1 = fmaf(v3.y, a[13], p1);
        p0 = fmaf(v3.z, a[14], p0); p1 = fmaf(v3.w, a[15], p1);
        float s = 0.5f * nrm - (p0 + p1);
        if (s < rv[7] && j != self) sinsN<8>(rv, ri, s, j);
    }

    // 8th smallest warp-wide
    float tau = 0.f;
    #pragma unroll
    for (int r = 0; r < 8; r++) {
        float v = rv[0]; int id = ri[0]; int ln = lane;
        wmin(v, id, ln);
        if (lane == ln) popN<8>(rv, ri);
        tau = v;
    }

    if (lane == 0) { g_tau[w] = tau; g_cnt[w] = 0; }
}

// ============ kernel B: filter all candidates against tau (norms computed inline) ============
__global__ __launch_bounds__(QPB) void filter_kernel(
    const float* __restrict__ emb0, const float* __restrict__ emb1,
    const int* __restrict__ idx0, const int* __restrict__ idx1)
{
    const int chunk = blockIdx.x;
    const int qg    = blockIdx.y;
    const int pass  = blockIdx.z;

    const float* emb = pass ? emb1 : emb0;
    const float4* emb4 = reinterpret_cast<const float4*>(emb);

    const int q    = qg * QPB + threadIdx.x;
    const int t2   = pass * B_Q + q;
    const int self = (pass ? idx1 : idx0)[q];
    const float tau = g_tau[t2];

    float a[E_DIM];
    load_q(emb4, self, a);

    __shared__ float4 smE[TILE * 4];
    __shared__ float  smN[TILE + 4];

    const int c0 = chunk * CHUNK;
    const int c1 = min(c0 + CHUNK, N_EMB);

    for (int base = c0; base < c1; base += TILE) {
        const int nc  = min(TILE, c1 - base);
        const int ncp = (nc + 3) & ~3;
        __syncthreads();
        // stage: each thread loads whole candidates (64B contiguous) + computes half-norm
        for (int c = threadIdx.x; c < ncp; c += QPB) {
            if (c < nc) {
                const float4* gE = emb4 + (size_t)(base + c) * 4;
                float4 v0 = gE[0], v1 = gE[1], v2 = gE[2], v3 = gE[3];
                smE[4*c] = v0; smE[4*c+1] = v1; smE[4*c+2] = v2; smE[4*c+3] = v3;
                float s = v0.x*v0.x + v0.y*v0.y + v0.z*v0.z + v0.w*v0.w
                        + v1.x*v1.x + v1.y*v1.y + v1.z*v1.z + v1.w*v1.w
                        + v2.x*v2.x + v2.y*v2.y + v2.z*v2.z + v2.w*v2.w
                        + v3.x*v3.x + v3.y*v3.y + v3.z*v3.z + v3.w*v3.w;
                smN[c] = 0.5f * s;
            } else {
                float4 z = make_float4(0.f, 0.f, 0.f, 0.f);
                smE[4*c] = z; smE[4*c+1] = z; smE[4*c+2] = z; smE[4*c+3] = z;
                smN[c] = FLT_BIG;
            }
        }
        __syncthreads();

        #pragma unroll 1
        for (int cc = 0; cc < ncp; cc += 4) {
            float s0 = smN[cc]     - dot16s(&smE[4*cc],      a);
            float s1 = smN[cc + 1] - dot16s(&smE[4*cc + 4],  a);
            float s2 = smN[cc + 2] - dot16s(&smE[4*cc + 8],  a);
            float s3 = smN[cc + 3] - dot16s(&smE[4*cc + 12], a);

            // self passes too (global minimum); removed later by index
            if (s0 <= tau) {
                int slot = atomicAdd(&g_cnt[t2], 1);
                if (slot < CAP) { g_fs[(size_t)t2 * CAP + slot] = s0; g_fj[(size_t)t2 * CAP + slot] = base + cc; }
            }
            if (s1 <= tau) {
                int slot = atomicAdd(&g_cnt[t2], 1);
                if (slot < CAP) { g_fs[(size_t)t2 * CAP + slot] = s1; g_fj[(size_t)t2 * CAP + slot] = base + cc + 1; }
            }
            if (s2 <= tau) {
                int slot = atomicAdd(&g_cnt[t2], 1);
                if (slot < CAP) { g_fs[(size_t)t2 * CAP + slot] = s2; g_fj[(size_t)t2 * CAP + slot] = base + cc + 2; }
            }
            if (s3 <= tau) {
                int slot = atomicAdd(&g_cnt[t2], 1);
                if (slot < CAP) { g_fs[(size_t)t2 * CAP + slot] = s3; g_fj[(size_t)t2 * CAP + slot] = base + cc + 3; }
            }
        }
    }
}

// ============ kernel C: exact top-20 of survivors + features + fused MLP ============
__global__ __launch_bounds__(128) void select_kernel(
    const float* __restrict__ emb0, const float* __restrict__ emb1,
    const float* __restrict__ rctx0, const float* __restrict__ rctx1,
    const int* __restrict__ idx0, const int* __restrict__ idx1,
    const float* __restrict__ mean_in, const float* __restrict__ std_in,
    const float* __restrict__ W1, const float* __restrict__ b1,
    const float* __restrict__ Wm, const float* __restrict__ bm,
    const float* __restrict__ Ws, const float* __restrict__ bs,
    float* __restrict__ out)
{
    __shared__ float sfe[2][8];

    const int wid  = threadIdx.x >> 5;
    const int lane = threadIdx.x & 31;
    const int ql   = wid >> 1;
    const int pass = wid & 1;
    const int q    = blockIdx.x * 2 + ql;
    const int t2   = pass * B_Q + q;

    const float* rctx = pass ? rctx1 : rctx0;
    const float* emb  = pass ? emb1 : emb0;
    const int    self = (pass ? idx1 : idx0)[q];

    // |a|^2 inline
    float na;
    {
        const float4* av = reinterpret_cast<const float4*>(emb) + (size_t)self * 4;
        float4 a0 = av[0], a1 = av[1], a2 = av[2], a3 = av[3];
        na = a0.x*a0.x + a0.y*a0.y + a0.z*a0.z + a0.w*a0.w
           + a1.x*a1.x + a1.y*a1.y + a1.z*a1.z + a1.w*a1.w
           + a2.x*a2.x + a2.y*a2.y + a2.z*a2.z + a2.w*a2.w
           + a3.x*a3.x + a3.y*a3.y + a3.z*a3.z + a3.w*a3.w;
    }

    int cnt = g_cnt[t2];
    if (cnt > CAP) cnt = CAP;

    float rv[10]; int ri[10];
    #pragma unroll
    for (int k = 0; k < 10; k++) { rv[k] = FLT_BIG; ri[k] = 0; }
    const float* FS = g_fs + (size_t)t2 * CAP;
    const int*   FJ = g_fj + (size_t)t2 * CAP;
    for (int i = lane; i < cnt; i += 32) {
        float s = FS[i];
        int  j = FJ[i];
        if (s < rv[9] && j != self) sinsN<10>(rv, ri, s, j);
    }

    float ms = 0.f; int mj = 0;
    #pragma unroll
    for (int r = 0; r < K_NN; r++) {
        float v = rv[0]; int id = ri[0]; int ln = lane;
        wmin(v, id, ln);
        if (lane == ln) popN<10>(rv, ri);
        if (lane == r) { ms = v; mj = id; }
    }

    const bool act = lane < K_NN;
    float w = 0.f, y = 0.f;
    if (act) {
        float d2 = fmaxf(fmaf(2.f, ms, na), 0.f);
        w = expf(-(sqrtf(d2) + 0.001f));
        y = rctx[(size_t)q * N_EMB + mj];
    }
    float f1 = w, f2n = w * y, ysum = y;
    #pragma unroll
    for (int off = 16; off; off >>= 1) {
        f1   += __shfl_xor_sync(FULLMASK, f1,   off);
        f2n  += __shfl_xor_sync(FULLMASK, f2n,  off);
        ysum += __shfl_xor_sync(FULLMASK, ysum, off);
    }
    float mean = ysum * (1.0f / K_NN);
    float d = act ? (y - mean) : 0.f;
    float var = d * d;
    #pragma unroll
    for (int off = 16; off; off >>= 1) var += __shfl_xor_sync(FULLMASK, var, off);
    float f3 = sqrtf(var * (1.0f / (K_NN - 1)));

    if (lane == 0) {
        sfe[ql][pass]     = f1;
        sfe[ql][2 + pass] = f2n / f1;
        sfe[ql][4 + pass] = f3;
        if (pass == 0) {
            sfe[ql][6] = mean_in[q];
            sfe[ql][7] = std_in[q];
        }
    }
    __syncthreads();

    if (wid < 2) {
        const int mq = blockIdx.x * 2 + wid;
        float f[8];
        #pragma unroll
        for (int i = 0; i < 8; i++) f[i] = sfe[wid][i];

        float m = 0.f, sd = 0.f;
        #pragma unroll
        for (int half = 0; half < 2; half++) {
            int j = lane + half * 32;
            float acc = b1[j];
            #pragma unroll
            for (int i = 0; i < 8; i++) acc = fmaf(f[i], W1[i * 64 + j], acc);
            float h = fmaxf(acc, 0.f);
            m  = fmaf(h, Wm[j], m);
            sd = fmaf(h, Ws[j], sd);
        }
        #pragma unroll
        for (int off = 16; off; off >>= 1) {
            m  += __shfl_xor_sync(FULLMASK, m,  off);
            sd += __shfl_xor_sync(FULLMASK, sd, off);
        }
        if (lane == 0) {
            out[mq]       = m  + bm[0];
            out[B_Q + mq] = sd + bs[0];
        }
    }
}

// ---------------- launcher ----------------
extern "C" void kernel_launch(void* const* d_in, const int* in_sizes, int n_in,
                              void* d_out, int out_size)
{
    const float* emb0    = (const float*)d_in[0];
    const float* emb1    = (const float*)d_in[1];
    const float* rctx0   = (const float*)d_in[2];
    const float* rctx1   = (const float*)d_in[3];
    const int*   idx0    = (const int*)d_in[4];
    const int*   idx1    = (const int*)d_in[5];
    const float* mean_in = (const float*)d_in[6];
    const float* std_in  = (const float*)d_in[7];
    const float* W1      = (const float*)d_in[8];
    const float* b1      = (const float*)d_in[9];
    const float* Wm      = (const float*)d_in[10];
    const float* bm      = (const float*)d_in[11];
    const float* Ws      = (const float*)d_in[12];
    const float* bs      = (const float*)d_in[13];
    float* out = (float*)d_out;

    prep_kernel<<<128, 256>>>(emb0, emb1, idx0, idx1);

    dim3 g1(NCHUNK, B_Q / QPB, 2);
    filter_kernel<<<g1, QPB>>>(emb0, emb1, idx0, idx1);

    select_kernel<<<B_Q / 2, 128>>>(emb0, emb1, rctx0, rctx1, idx0, idx1,
                                    mean_in, std_in,
                                    W1, b1, Wm, bm, Ws, bs, out);
}

// round 6
// speedup vs baseline: 3.9895x; 1.0030x over previous
#include <cuda_runtime.h>

// ---------------- problem constants ----------------
#define N_EMB   50000
#define B_Q     512
#define E_DIM   16
#define K_NN    20
#define NCHUNK  64
#define CHUNK   782           // 64*782 = 50048 >= 50000
#define TILE    256
#define QPB     128
#define CAP     1024
#define FLT_BIG 3.402823466e+38f
#define FULLMASK 0xffffffffu

// ---------------- scratch ----------------
__device__ float g_tau [2 * B_Q];
__device__ int   g_cnt [2 * B_Q];
__device__ float g_fs  [2 * B_Q * CAP];
__device__ int   g_fj  [2 * B_Q * CAP];

// ---------------- helpers ----------------
template <int S>
__device__ __forceinline__ void sinsN(float (&rv)[S], int (&ri)[S], float s, int j) {
    float cv = s; int ci = j;
    #pragma unroll
    for (int k = 0; k < S; k++) {
        bool sm = cv < rv[k];
        float tv = rv[k]; int ti = ri[k];
        rv[k] = sm ? cv : rv[k];
        ri[k] = sm ? ci : ri[k];
        cv = sm ? tv : cv;
        ci = sm ? ti : ci;
    }
}

template <int S>
__device__ __forceinline__ void popN(float (&rv)[S], int (&ri)[S]) {
    #pragma unroll
    for (int k = 0; k < S - 1; k++) { rv[k] = rv[k + 1]; ri[k] = ri[k + 1]; }
    rv[S - 1] = FLT_BIG; ri[S - 1] = 0;
}

__device__ __forceinline__ void wmin(float& v, int& id, int& ln) {
    #pragma unroll
    for (int off = 16; off; off >>= 1) {
        float ov = __shfl_xor_sync(FULLMASK, v,  off);
        int  oid = __shfl_xor_sync(FULLMASK, id, off);
        int  oln = __shfl_xor_sync(FULLMASK, ln, off);
        if (ov < v) { v = ov; id = oid; ln = oln; }
    }
}

__device__ __forceinline__ float dot16s(const float4* __restrict__ e, const float a[E_DIM]) {
    float4 v0 = e[0], v1 = e[1], v2 = e[2], v3 = e[3];
    float p0 = v0.x * a[0];
    float p1 = v0.y * a[1];
    p0 = fmaf(v0.z, a[2],  p0); p1 = fmaf(v0.w, a[3],  p1);
    p0 = fmaf(v1.x, a[4],  p0); p1 = fmaf(v1.y, a[5],  p1);
    p0 = fmaf(v1.z, a[6],  p0); p1 = fmaf(v1.w, a[7],  p1);
    p0 = fmaf(v2.x, a[8],  p0); p1 = fmaf(v2.y, a[9],  p1);
    p0 = fmaf(v2.z, a[10], p0); p1 = fmaf(v2.w, a[11], p1);
    p0 = fmaf(v3.x, a[12], p0); p1 = fmaf(v3.y, a[13], p1);
    p0 = fmaf(v3.z, a[14], p0); p1 = fmaf(v3.w, a[15], p1);
    return p0 + p1;
}

__device__ __forceinline__ void load_q(const float4* emb4, int self, float (&a)[E_DIM]) {
    const float4* av = emb4 + (size_t)self * 4;
    float4 a0 = av[0], a1 = av[1], a2 = av[2], a3 = av[3];
    a[0]=a0.x; a[1]=a0.y; a[2]=a0.z; a[3]=a0.w;
    a[4]=a1.x; a[5]=a1.y; a[6]=a1.z; a[7]=a1.w;
    a[8]=a2.x; a[9]=a2.y; a[10]=a2.z; a[11]=a2.w;
    a[12]=a3.x; a[13]=a3.y; a[14]=a3.z; a[15]=a3.w;
}

// ============ kernel A: per-(pass,query) tau from contiguous 1024-sample ============
// one warp per (pass,query); 128 blocks x 256 threads
__global__ __launch_bounds__(256) void prep_kernel(
    const float* __restrict__ emb0, const float* __restrict__ emb1,
    const int* __restrict__ idx0, const int* __restrict__ idx1)
{
    const int wid  = threadIdx.x >> 5;
    const int lane = threadIdx.x & 31;
    const int w    = blockIdx.x * 8 + wid;  // [0, 1024)
    const int pass = w >> 9;
    const int q    = w & (B_Q - 1);

    const float* emb  = pass ? emb1 : emb0;
    const int    self = (pass ? idx1 : idx0)[q];
    const float4* emb4 = reinterpret_cast<const float4*>(emb);

    float a[E_DIM];
    load_q(emb4, self, a);

    float rv[8]; int ri[8];
    #pragma unroll
    for (int k = 0; k < 8; k++) { rv[k] = FLT_BIG; ri[k] = 0; }

    #pragma unroll 4
    for (int i = 0; i < 32; i++) {
        int j = i * 32 + lane;          // contiguous window [0,1024), L1/L2 resident
        const float4* e = emb4 + (size_t)j * 4;
        float4 v0 = e[0], v1 = e[1], v2 = e[2], v3 = e[3];
        float nrm = v0.x*v0.x + v0.y*v0.y + v0.z*v0.z + v0.w*v0.w
                  + v1.x*v1.x + v1.y*v1.y + v1.z*v1.z + v1.w*v1.w
                  + v2.x*v2.x + v2.y*v2.y + v2.z*v2.z + v2.w*v2.w
                  + v3.x*v3.x + v3.y*v3.y + v3.z*v3.z + v3.w*v3.w;
        float p0 = v0.x * a[0];
        float p1 = v0.y * a[1];
        p0 = fmaf(v0.z, a[2],  p0); p1 = fmaf(v0.w, a[3],  p1);
        p0 = fmaf(v1.x, a[4],  p0); p1 = fmaf(v1.y, a[5],  p1);
        p0 = fmaf(v1.z, a[6],  p0); p1 = fmaf(v1.w, a[7],  p1);
        p0 = fmaf(v2.x, a[8],  p0); p1 = fmaf(v2.y, a[9],  p1);
        p0 = fmaf(v2.z, a[10], p0); p1 = fmaf(v2.w, a[11], p1);
        p0 = fmaf(v3.x, a[12], p0); p1 = fmaf(v3.y, a[13], p1);
        p0 = fmaf(v3.z, a[14], p0); p1 = fmaf(v3.w, a[15], p1);
        float s = 0.5f * nrm - (p0 + p1);
        if (s < rv[7] && j != self) sinsN<8>(rv, ri, s, j);
    }

    // 8th smallest warp-wide
    float tau = 0.f;
    #pragma unroll
    for (int r = 0; r < 8; r++) {
        float v = rv[0]; int id = ri[0]; int ln = lane;
        wmin(v, id, ln);
        if (lane == ln) popN<8>(rv, ri);
        tau = v;
    }

    if (lane == 0) { g_tau[w] = tau; g_cnt[w] = 0; }
}

// ============ kernel B: filter all candidates against tau (norms computed inline) ============
__global__ __launch_bounds__(QPB) void filter_kernel(
    const float* __restrict__ emb0, const float* __restrict__ emb1,
    const int* __restrict__ idx0, const int* __restrict__ idx1)
{
    const int chunk = blockIdx.x;
    const int qg    = blockIdx.y;
    const int pass  = blockIdx.z;

    const float* emb = pass ? emb1 : emb0;
    const float4* emb4 = reinterpret_cast<const float4*>(emb);

    const int q    = qg * QPB + threadIdx.x;
    const int t2   = pass * B_Q + q;
    const int self = (pass ? idx1 : idx0)[q];
    const float tau = g_tau[t2];

    float a[E_DIM];
    load_q(emb4, self, a);

    __shared__ float4 smE[TILE * 4];
    __shared__ float  smN[TILE + 4];

    const int c0 = chunk * CHUNK;
    const int c1 = min(c0 + CHUNK, N_EMB);

    for (int base = c0; base < c1; base += TILE) {
        const int nc  = min(TILE, c1 - base);
        const int ncp = (nc + 3) & ~3;
        __syncthreads();
        // stage: each thread loads whole candidates (64B contiguous) + computes half-norm
        for (int c = threadIdx.x; c < ncp; c += QPB) {
            if (c < nc) {
                const float4* gE = emb4 + (size_t)(base + c) * 4;
                float4 v0 = gE[0], v1 = gE[1], v2 = gE[2], v3 = gE[3];
                smE[4*c] = v0; smE[4*c+1] = v1; smE[4*c+2] = v2; smE[4*c+3] = v3;
                float s = v0.x*v0.x + v0.y*v0.y + v0.z*v0.z + v0.w*v0.w
                        + v1.x*v1.x + v1.y*v1.y + v1.z*v1.z + v1.w*v1.w
                        + v2.x*v2.x + v2.y*v2.y + v2.z*v2.z + v2.w*v2.w
                        + v3.x*v3.x + v3.y*v3.y + v3.z*v3.z + v3.w*v3.w;
                smN[c] = 0.5f * s;
            } else {
                float4 z = make_float4(0.f, 0.f, 0.f, 0.f);
                smE[4*c] = z; smE[4*c+1] = z; smE[4*c+2] = z; smE[4*c+3] = z;
                smN[c] = FLT_BIG;
            }
        }
        __syncthreads();

        #pragma unroll 1
        for (int cc = 0; cc < ncp; cc += 4) {
            float s0 = smN[cc]     - dot16s(&smE[4*cc],      a);
            float s1 = smN[cc + 1] - dot16s(&smE[4*cc + 4],  a);
            float s2 = smN[cc + 2] - dot16s(&smE[4*cc + 8],  a);
            float s3 = smN[cc + 3] - dot16s(&smE[4*cc + 12], a);

            // self passes too (global minimum); removed later by index
            if (s0 <= tau) {
                int slot = atomicAdd(&g_cnt[t2], 1);
                if (slot < CAP) { g_fs[(size_t)t2 * CAP + slot] = s0; g_fj[(size_t)t2 * CAP + slot] = base + cc; }
            }
            if (s1 <= tau) {
                int slot = atomicAdd(&g_cnt[t2], 1);
                if (slot < CAP) { g_fs[(size_t)t2 * CAP + slot] = s1; g_fj[(size_t)t2 * CAP + slot] = base + cc + 1; }
            }
            if (s2 <= tau) {
                int slot = atomicAdd(&g_cnt[t2], 1);
                if (slot < CAP) { g_fs[(size_t)t2 * CAP + slot] = s2; g_fj[(size_t)t2 * CAP + slot] = base + cc + 2; }
            }
            if (s3 <= tau) {
                int slot = atomicAdd(&g_cnt[t2], 1);
                if (slot < CAP) { g_fs[(size_t)t2 * CAP + slot] = s3; g_fj[(size_t)t2 * CAP + slot] = base + cc + 3; }
            }
        }
    }
}

// ============ kernel C: exact top-20 of survivors + features + fused MLP ============
__global__ __launch_bounds__(128) void select_kernel(
    const float* __restrict__ emb0, const float* __restrict__ emb1,
    const float* __restrict__ rctx0, const float* __restrict__ rctx1,
    const int* __restrict__ idx0, const int* __restrict__ idx1,
    const float* __restrict__ mean_in, const float* __restrict__ std_in,
    const float* __restrict__ W1, const float* __restrict__ b1,
    const float* __restrict__ Wm, const float* __restrict__ bm,
    const float* __restrict__ Ws, const float* __restrict__ bs,
    float* __restrict__ out)
{
    __shared__ float sfe[2][8];

    const int wid  = threadIdx.x >> 5;
    const int lane = threadIdx.x & 31;
    const int ql   = wid >> 1;
    const int pass = wid & 1;
    const int q    = blockIdx.x * 2 + ql;
    const int t2   = pass * B_Q + q;

    const float* rctx = pass ? rctx1 : rctx0;
    const float* emb  = pass ? emb1 : emb0;
    const int    self = (pass ? idx1 : idx0)[q];

    // |a|^2 inline
    float na;
    {
        const float4* av = reinterpret_cast<const float4*>(emb) + (size_t)self * 4;
        float4 a0 = av[0], a1 = av[1], a2 = av[2], a3 = av[3];
        na = a0.x*a0.x + a0.y*a0.y + a0.z*a0.z + a0.w*a0.w
           + a1.x*a1.x + a1.y*a1.y + a1.z*a1.z + a1.w*a1.w
           + a2.x*a2.x + a2.y*a2.y + a2.z*a2.z + a2.w*a2.w
           + a3.x*a3.x + a3.y*a3.y + a3.z*a3.z + a3.w*a3.w;
    }

    int cnt = g_cnt[t2];
    if (cnt > CAP) cnt = CAP;

    float rv[10]; int ri[10];
    #pragma unroll
    for (int k = 0; k < 10; k++) { rv[k] = FLT_BIG; ri[k] = 0; }
    const float* FS = g_fs + (size_t)t2 * CAP;
    const int*   FJ = g_fj + (size_t)t2 * CAP;
    for (int i = lane; i < cnt; i += 32) {
        float s = FS[i];
        int  j = FJ[i];
        if (s < rv[9] && j != self) sinsN<10>(rv, ri, s, j);
    }

    float ms = 0.f; int mj = 0;
    #pragma unroll
    for (int r = 0; r < K_NN; r++) {
        float v = rv[0]; int id = ri[0]; int ln = lane;
        wmin(v, id, ln);
        if (lane == ln) popN<10>(rv, ri);
        if (lane == r) { ms = v; mj = id; }
    }

    const bool act = lane < K_NN;
    float w = 0.f, y = 0.f;
    if (act) {
        float d2 = fmaxf(fmaf(2.f, ms, na), 0.f);
        w = expf(-(sqrtf(d2) + 0.001f));
        y = rctx[(size_t)q * N_EMB + mj];
    }
    float f1 = w, f2n = w * y, ysum = y;
    #pragma unroll
    for (int off = 16; off; off >>= 1) {
        f1   += __shfl_xor_sync(FULLMASK, f1,   off);
        f2n  += __shfl_xor_sync(FULLMASK, f2n,  off);
        ysum += __shfl_xor_sync(FULLMASK, ysum, off);
    }
    float mean = ysum * (1.0f / K_NN);
    float d = act ? (y - mean) : 0.f;
    float var = d * d;
    #pragma unroll
    for (int off = 16; off; off >>= 1) var += __shfl_xor_sync(FULLMASK, var, off);
    float f3 = sqrtf(var * (1.0f / (K_NN - 1)));

    if (lane == 0) {
        sfe[ql][pass]     = f1;
        sfe[ql][2 + pass] = f2n / f1;
        sfe[ql][4 + pass] = f3;
        if (pass == 0) {
            sfe[ql][6] = mean_in[q];
            sfe[ql][7] = std_in[q];
        }
    }
    __syncthreads();

    if (wid < 2) {
        const int mq = blockIdx.x * 2 + wid;
        float f[8];
        #pragma unroll
        for (int i = 0; i < 8; i++) f[i] = sfe[wid][i];

        float m = 0.f, sd = 0.f;
        #pragma unroll
        for (int half = 0; half < 2; half++) {
            int j = lane + half * 32;
            float acc = b1[j];
            #pragma unroll
            for (int i = 0; i < 8; i++) acc = fmaf(f[i], W1[i * 64 + j], acc);
            float h = fmaxf(acc, 0.f);
            m  = fmaf(h, Wm[j], m);
            sd = fmaf(h, Ws[j], sd);
        }
        #pragma unroll
        for (int off = 16; off; off >>= 1) {
            m  += __shfl_xor_sync(FULLMASK, m,  off);
            sd += __shfl_xor_sync(FULLMASK, sd, off);
        }
        if (lane == 0) {
            out[mq]       = m  + bm[0];
            out[B_Q + mq] = sd + bs[0];
        }
    }
}

// ---------------- launcher ----------------
extern "C" void kernel_launch(void* const* d_in, const int* in_sizes, int n_in,
                              void* d_out, int out_size)
{
    const float* emb0    = (const float*)d_in[0];
    const float* emb1    = (const float*)d_in[1];
    const float* rctx0   = (const float*)d_in[2];
    const float* rctx1   = (const float*)d_in[3];
    const int*   idx0    = (const int*)d_in[4];
    const int*   idx1    = (const int*)d_in[5];
    const float* mean_in = (const float*)d_in[6];
    const float* std_in  = (const float*)d_in[7];
    const float* W1      = (const float*)d_in[8];
    const float* b1      = (const float*)d_in[9];
    const float* Wm      = (const float*)d_in[10];
    const float* bm      = (const float*)d_in[11];
    const float* Ws      = (const float*)d_in[12];
    const float* bs      = (const float*)d_in[13];
    float* out = (float*)d_out;

    prep_kernel<<<128, 256>>>(emb0, emb1, idx0, idx1);

    dim3 g1(NCHUNK, B_Q / QPB, 2);
    filter_kernel<<<g1, QPB>>>(emb0, emb1, idx0, idx1);

    select_kernel<<<B_Q / 2, 128>>>(emb0, emb1, rctx0, rctx1, idx0, idx1,
                                    mean_in, std_in,
                                    W1, b1, Wm, bm, Ws, bs, out);
}

// round 7
// speedup vs baseline: 4.3225x; 1.0835x over previous
#include <cuda_runtime.h>

// ---------------- problem constants ----------------
#define N_EMB   50000
#define B_Q     512
#define E_DIM   16
#define K_NN    20
#define NCHUNK  64
#define CHUNK   782           // 64*782 = 50048 >= 50000
#define TILE    256
#define QPB     128
#define CAP     1024
#define FLT_BIG 3.402823466e+38f
#define FULLMASK 0xffffffffu

typedef unsigned long long u64;

// packed f32x2 helpers (FFMA2 path — ptxas won't fuse this from C++)
#define FMA2(d, a, b, c) asm("fma.rn.f32x2 %0, %1, %2, %3;" : "=l"(d) : "l"(a), "l"(b), "l"(c))
#define PACK2(d, lo, hi) asm("mov.b64 %0, {%1, %2};" : "=l"(d) : "f"(lo), "f"(hi))
#define UNPACK2(lo, hi, v) asm("mov.b64 {%0, %1}, %2;" : "=f"(lo), "=f"(hi) : "l"(v))

// ---------------- scratch ----------------
__device__ float g_tau [2 * B_Q];
__device__ int   g_cnt [2 * B_Q];
__device__ float g_fs  [2 * B_Q * CAP];
__device__ int   g_fj  [2 * B_Q * CAP];

// ---------------- helpers ----------------
template <int S>
__device__ __forceinline__ void sinsN(float (&rv)[S], int (&ri)[S], float s, int j) {
    float cv = s; int ci = j;
    #pragma unroll
    for (int k = 0; k < S; k++) {
        bool sm = cv < rv[k];
        float tv = rv[k]; int ti = ri[k];
        rv[k] = sm ? cv : rv[k];
        ri[k] = sm ? ci : ri[k];
        cv = sm ? tv : cv;
        ci = sm ? ti : ci;
    }
}

template <int S>
__device__ __forceinline__ void popN(float (&rv)[S], int (&ri)[S]) {
    #pragma unroll
    for (int k = 0; k < S - 1; k++) { rv[k] = rv[k + 1]; ri[k] = ri[k + 1]; }
    rv[S - 1] = FLT_BIG; ri[S - 1] = 0;
}

__device__ __forceinline__ void wmin(float& v, int& id, int& ln) {
    #pragma unroll
    for (int off = 16; off; off >>= 1) {
        float ov = __shfl_xor_sync(FULLMASK, v,  off);
        int  oid = __shfl_xor_sync(FULLMASK, id, off);
        int  oln = __shfl_xor_sync(FULLMASK, ln, off);
        if (ov < v) { v = ov; id = oid; ln = oln; }
    }
}

// load query row, produce negated packed f32x2 halves
__device__ __forceinline__ void load_q_neg2(const float* emb, int self, u64 (&an)[8]) {
    const float4* av = reinterpret_cast<const float4*>(emb) + (size_t)self * 4;
    float4 a0 = av[0], a1 = av[1], a2 = av[2], a3 = av[3];
    PACK2(an[0], -a0.x, -a0.y); PACK2(an[1], -a0.z, -a0.w);
    PACK2(an[2], -a1.x, -a1.y); PACK2(an[3], -a1.z, -a1.w);
    PACK2(an[4], -a2.x, -a2.y); PACK2(an[5], -a2.z, -a2.w);
    PACK2(an[6], -a3.x, -a3.y); PACK2(an[7], -a3.z, -a3.w);
}

// s = norm_init - a.e  via packed fma; e given as 4 x ulonglong2 (= 8 f32x2)
__device__ __forceinline__ float score8(const ulonglong2 u[4], const u64 an[8], u64 acc0_init) {
    u64 acc0 = acc0_init, acc1 = 0ull;  // (norm, 0), (0, 0)
    FMA2(acc0, u[0].x, an[0], acc0); FMA2(acc1, u[0].y, an[1], acc1);
    FMA2(acc0, u[1].x, an[2], acc0); FMA2(acc1, u[1].y, an[3], acc1);
    FMA2(acc0, u[2].x, an[4], acc0); FMA2(acc1, u[2].y, an[5], acc1);
    FMA2(acc0, u[3].x, an[6], acc0); FMA2(acc1, u[3].y, an[7], acc1);
    float l0, h0, l1, h1;
    UNPACK2(l0, h0, acc0);
    UNPACK2(l1, h1, acc1);
    return (l0 + h0) + (l1 + h1);
}

// ============ kernel A: per-(pass,query) tau from contiguous 1024-sample ============
// one warp per (pass,query); 256 blocks x 128 threads
__global__ __launch_bounds__(128) void prep_kernel(
    const float* __restrict__ emb0, const float* __restrict__ emb1,
    const int* __restrict__ idx0, const int* __restrict__ idx1)
{
    const int wid  = threadIdx.x >> 5;
    const int lane = threadIdx.x & 31;
    const int w    = blockIdx.x * 4 + wid;  // [0, 1024)
    const int pass = w >> 9;
    const int q    = w & (B_Q - 1);

    const float* emb  = pass ? emb1 : emb0;
    const int    self = (pass ? idx1 : idx0)[q];

    u64 an[8];
    load_q_neg2(emb, self, an);
    u64 halfp;
    PACK2(halfp, 0.5f, 0.5f);

    float rv[8]; int ri[8];
    #pragma unroll
    for (int k = 0; k < 8; k++) { rv[k] = FLT_BIG; ri[k] = 0; }

    const ulonglong2* emb2 = reinterpret_cast<const ulonglong2*>(emb);

    #pragma unroll 4
    for (int i = 0; i < 32; i++) {
        int j = i * 32 + lane;          // contiguous window [0,1024), L1/L2 resident
        const ulonglong2* p = emb2 + (size_t)j * 4;
        ulonglong2 u[4] = { p[0], p[1], p[2], p[3] };
        // s = sum e_k*(0.5 e_k - a_k):  h = fma(e, 0.5, -a); acc = fma(e, h, acc)
        u64 h0, h1, h2, h3, h4, h5, h6, h7;
        FMA2(h0, u[0].x, halfp, an[0]); FMA2(h1, u[0].y, halfp, an[1]);
        FMA2(h2, u[1].x, halfp, an[2]); FMA2(h3, u[1].y, halfp, an[3]);
        FMA2(h4, u[2].x, halfp, an[4]); FMA2(h5, u[2].y, halfp, an[5]);
        FMA2(h6, u[3].x, halfp, an[6]); FMA2(h7, u[3].y, halfp, an[7]);
        u64 acc0 = 0ull, acc1 = 0ull;
        FMA2(acc0, u[0].x, h0, acc0); FMA2(acc1, u[0].y, h1, acc1);
        FMA2(acc0, u[1].x, h2, acc0); FMA2(acc1, u[1].y, h3, acc1);
        FMA2(acc0, u[2].x, h4, acc0); FMA2(acc1, u[2].y, h5, acc1);
        FMA2(acc0, u[3].x, h6, acc0); FMA2(acc1, u[3].y, h7, acc1);
        float l0, hh0, l1, hh1;
        UNPACK2(l0, hh0, acc0);
        UNPACK2(l1, hh1, acc1);
        float s = (l0 + hh0) + (l1 + hh1);
        if (s < rv[7] && j != self) sinsN<8>(rv, ri, s, j);
    }

    // 8th smallest warp-wide
    float tau = 0.f;
    #pragma unroll
    for (int r = 0; r < 8; r++) {
        float v = rv[0]; int id = ri[0]; int ln = lane;
        wmin(v, id, ln);
        if (lane == ln) popN<8>(rv, ri);
        tau = v;
    }

    if (lane == 0) { g_tau[w] = tau; g_cnt[w] = 0; }
}

// ============ kernel B: filter all candidates against tau ============
__global__ __launch_bounds__(QPB) void filter_kernel(
    const float* __restrict__ emb0, const float* __restrict__ emb1,
    const int* __restrict__ idx0, const int* __restrict__ idx1)
{
    const int chunk = blockIdx.x;
    const int qg    = blockIdx.y;
    const int pass  = blockIdx.z;

    const float* emb = pass ? emb1 : emb0;
    const float4* emb4 = reinterpret_cast<const float4*>(emb);

    const int q    = qg * QPB + threadIdx.x;
    const int t2   = pass * B_Q + q;
    const int self = (pass ? idx1 : idx0)[q];
    const float tau = g_tau[t2];

    u64 an[8];
    load_q_neg2(emb, self, an);

    __shared__ float4 smE[TILE * 4];
    __shared__ u64    smN[TILE + 4];   // packed (0.5*norm, 0)

    const int c0 = chunk * CHUNK;
    const int c1 = min(c0 + CHUNK, N_EMB);

    for (int base = c0; base < c1; base += TILE) {
        const int nc  = min(TILE, c1 - base);
        const int ncp = (nc + 3) & ~3;
        __syncthreads();
        for (int c = threadIdx.x; c < ncp; c += QPB) {
            if (c < nc) {
                const float4* gE = emb4 + (size_t)(base + c) * 4;
                float4 v0 = gE[0], v1 = gE[1], v2 = gE[2], v3 = gE[3];
                smE[4*c] = v0; smE[4*c+1] = v1; smE[4*c+2] = v2; smE[4*c+3] = v3;
                float s = v0.x*v0.x + v0.y*v0.y + v0.z*v0.z + v0.w*v0.w
                        + v1.x*v1.x + v1.y*v1.y + v1.z*v1.z + v1.w*v1.w
                        + v2.x*v2.x + v2.y*v2.y + v2.z*v2.z + v2.w*v2.w
                        + v3.x*v3.x + v3.y*v3.y + v3.z*v3.z + v3.w*v3.w;
                u64 pn; PACK2(pn, 0.5f * s, 0.f);
                smN[c] = pn;
            } else {
                float4 z = make_float4(0.f, 0.f, 0.f, 0.f);
                smE[4*c] = z; smE[4*c+1] = z; smE[4*c+2] = z; smE[4*c+3] = z;
                u64 pn; PACK2(pn, FLT_BIG, 0.f);
                smN[c] = pn;
            }
        }
        __syncthreads();

        const ulonglong2* smE2 = reinterpret_cast<const ulonglong2*>(smE);

        #pragma unroll 1
        for (int cc = 0; cc < ncp; cc += 4) {
            ulonglong2 u0[4] = { smE2[4*cc],      smE2[4*cc + 1],  smE2[4*cc + 2],  smE2[4*cc + 3]  };
            ulonglong2 u1[4] = { smE2[4*cc + 4],  smE2[4*cc + 5],  smE2[4*cc + 6],  smE2[4*cc + 7]  };
            ulonglong2 u2[4] = { smE2[4*cc + 8],  smE2[4*cc + 9],  smE2[4*cc + 10], smE2[4*cc + 11] };
            ulonglong2 u3[4] = { smE2[4*cc + 12], smE2[4*cc + 13], smE2[4*cc + 14], smE2[4*cc + 15] };
            float s0 = score8(u0, an, smN[cc]);
            float s1 = score8(u1, an, smN[cc + 1]);
            float s2 = score8(u2, an, smN[cc + 2]);
            float s3 = score8(u3, an, smN[cc + 3]);

            // self passes too (global minimum); removed later by index
            if (s0 <= tau) {
                int slot = atomicAdd(&g_cnt[t2], 1);
                if (slot < CAP) { g_fs[(size_t)t2 * CAP + slot] = s0; g_fj[(size_t)t2 * CAP + slot] = base + cc; }
            }
            if (s1 <= tau) {
                int slot = atomicAdd(&g_cnt[t2], 1);
                if (slot < CAP) { g_fs[(size_t)t2 * CAP + slot] = s1; g_fj[(size_t)t2 * CAP + slot] = base + cc + 1; }
            }
            if (s2 <= tau) {
                int slot = atomicAdd(&g_cnt[t2], 1);
                if (slot < CAP) { g_fs[(size_t)t2 * CAP + slot] = s2; g_fj[(size_t)t2 * CAP + slot] = base + cc + 2; }
            }
            if (s3 <= tau) {
                int slot = atomicAdd(&g_cnt[t2], 1);
                if (slot < CAP) { g_fs[(size_t)t2 * CAP + slot] = s3; g_fj[(size_t)t2 * CAP + slot] = base + cc + 3; }
            }
        }
    }
}

// ============ kernel C: exact top-20 of survivors + features + fused MLP ============
__global__ __launch_bounds__(128) void select_kernel(
    const float* __restrict__ emb0, const float* __restrict__ emb1,
    const float* __restrict__ rctx0, const float* __restrict__ rctx1,
    const int* __restrict__ idx0, const int* __restrict__ idx1,
    const float* __restrict__ mean_in, const float* __restrict__ std_in,
    const float* __restrict__ W1, const float* __restrict__ b1,
    const float* __restrict__ Wm, const float* __restrict__ bm,
    const float* __restrict__ Ws, const float* __restrict__ bs,
    float* __restrict__ out)
{
    __shared__ float sfe[2][8];

    const int wid  = threadIdx.x >> 5;
    const int lane = threadIdx.x & 31;
    const int ql   = wid >> 1;
    const int pass = wid & 1;
    const int q    = blockIdx.x * 2 + ql;
    const int t2   = pass * B_Q + q;

    const float* rctx = pass ? rctx1 : rctx0;
    const float* emb  = pass ? emb1 : emb0;
    const int    self = (pass ? idx1 : idx0)[q];

    float na;
    {
        const float4* av = reinterpret_cast<const float4*>(emb) + (size_t)self * 4;
        float4 a0 = av[0], a1 = av[1], a2 = av[2], a3 = av[3];
        na = a0.x*a0.x + a0.y*a0.y + a0.z*a0.z + a0.w*a0.w
           + a1.x*a1.x + a1.y*a1.y + a1.z*a1.z + a1.w*a1.w
           + a2.x*a2.x + a2.y*a2.y + a2.z*a2.z + a2.w*a2.w
           + a3.x*a3.x + a3.y*a3.y + a3.z*a3.z + a3.w*a3.w;
    }

    int cnt = g_cnt[t2];
    if (cnt > CAP) cnt = CAP;

    float rv[10]; int ri[10];
    #pragma unroll
    for (int k = 0; k < 10; k++) { rv[k] = FLT_BIG; ri[k] = 0; }
    const float* FS = g_fs + (size_t)t2 * CAP;
    const int*   FJ = g_fj + (size_t)t2 * CAP;
    for (int i = lane; i < cnt; i += 32) {
        float s = FS[i];
        int  j = FJ[i];
        if (s < rv[9] && j != self) sinsN<10>(rv, ri, s, j);
    }

    float ms = 0.f; int mj = 0;
    #pragma unroll
    for (int r = 0; r < K_NN; r++) {
        float v = rv[0]; int id = ri[0]; int ln = lane;
        wmin(v, id, ln);
        if (lane == ln) popN<10>(rv, ri);
        if (lane == r) { ms = v; mj = id; }
    }

    const bool act = lane < K_NN;
    float w = 0.f, y = 0.f;
    if (act) {
        float d2 = fmaxf(fmaf(2.f, ms, na), 0.f);
        w = expf(-(sqrtf(d2) + 0.001f));
        y = rctx[(size_t)q * N_EMB + mj];
    }
    float f1 = w, f2n = w * y, ysum = y;
    #pragma unroll
    for (int off = 16; off; off >>= 1) {
        f1   += __shfl_xor_sync(FULLMASK, f1,   off);
        f2n  += __shfl_xor_sync(FULLMASK, f2n,  off);
        ysum += __shfl_xor_sync(FULLMASK, ysum, off);
    }
    float mean = ysum * (1.0f / K_NN);
    float d = act ? (y - mean) : 0.f;
    float var = d * d;
    #pragma unroll
    for (int off = 16; off; off >>= 1) var += __shfl_xor_sync(FULLMASK, var, off);
    float f3 = sqrtf(var * (1.0f / (K_NN - 1)));

    if (lane == 0) {
        sfe[ql][pass]     = f1;
        sfe[ql][2 + pass] = f2n / f1;
        sfe[ql][4 + pass] = f3;
        if (pass == 0) {
            sfe[ql][6] = mean_in[q];
            sfe[ql][7] = std_in[q];
        }
    }
    __syncthreads();

    if (wid < 2) {
        const int mq = blockIdx.x * 2 + wid;
        float f[8];
        #pragma unroll
        for (int i = 0; i < 8; i++) f[i] = sfe[wid][i];

        float m = 0.f, sd = 0.f;
        #pragma unroll
        for (int half = 0; half < 2; half++) {
            int j = lane + half * 32;
            float acc = b1[j];
            #pragma unroll
            for (int i = 0; i < 8; i++) acc = fmaf(f[i], W1[i * 64 + j], acc);
            float h = fmaxf(acc, 0.f);
            m  = fmaf(h, Wm[j], m);
            sd = fmaf(h, Ws[j], sd);
        }
        #pragma unroll
        for (int off = 16; off; off >>= 1) {
            m  += __shfl_xor_sync(FULLMASK, m,  off);
            sd += __shfl_xor_sync(FULLMASK, sd, off);
        }
        if (lane == 0) {
            out[mq]       = m  + bm[0];
            out[B_Q + mq] = sd + bs[0];
        }
    }
}

// ---------------- launcher ----------------
extern "C" void kernel_launch(void* const* d_in, const int* in_sizes, int n_in,
                              void* d_out, int out_size)
{
    const float* emb0    = (const float*)d_in[0];
    const float* emb1    = (const float*)d_in[1];
    const float* rctx0   = (const float*)d_in[2];
    const float* rctx1   = (const float*)d_in[3];
    const int*   idx0    = (const int*)d_in[4];
    const int*   idx1    = (const int*)d_in[5];
    const float* mean_in = (const float*)d_in[6];
    const float* std_in  = (const float*)d_in[7];
    const float* W1      = (const float*)d_in[8];
    const float* b1      = (const float*)d_in[9];
    const float* Wm      = (const float*)d_in[10];
    const float* bm      = (const float*)d_in[11];
    const float* Ws      = (const float*)d_in[12];
    const float* bs      = (const float*)d_in[13];
    float* out = (float*)d_out;

    prep_kernel<<<256, 128>>>(emb0, emb1, idx0, idx1);

    dim3 g1(NCHUNK, B_Q / QPB, 2);
    filter_kernel<<<g1, QPB>>>(emb0, emb1, idx0, idx1);

    select_kernel<<<B_Q / 2, 128>>>(emb0, emb1, rctx0, rctx1, idx0, idx1,
                                    mean_in, std_in,
                                    W1, b1, Wm, bm, Ws, bs, out);
}

// round 8
// speedup vs baseline: 4.9921x; 1.1549x over previous
#include <cuda_runtime.h>

// ---------------- problem constants ----------------
#define N_EMB   50000
#define B_Q     512
#define E_DIM   16
#define K_NN    20
#define NCHUNK  64
#define CHUNK   782           // 64*782 = 50048 >= 50000
#define TILE    256
#define QPB     128
#define CAP     1024
#define BUFD    24            // per-thread smem survivor slots per tile
#define WIN     1024          // prep sample window
#define FLT_BIG 3.402823466e+38f
#define FULLMASK 0xffffffffu

typedef unsigned long long u64;

// packed f32x2 helpers
#define FMA2(d, a, b, c) asm("fma.rn.f32x2 %0, %1, %2, %3;" : "=l"(d) : "l"(a), "l"(b), "l"(c))
#define PACK2(d, lo, hi) asm("mov.b64 %0, {%1, %2};" : "=l"(d) : "f"(lo), "f"(hi))
#define UNPACK2(lo, hi, v) asm("mov.b64 {%0, %1}, %2;" : "=f"(lo), "=f"(hi) : "l"(v))
#define PACKFI(d, f, i) asm("mov.b64 %0, {%1, %2};" : "=l"(d) : "f"(f), "r"(i))
#define UNPACKFI(f, i, v) asm("mov.b64 {%0, %1}, %2;" : "=f"(f), "=r"(i) : "l"(v))

// ---------------- scratch ----------------
__device__ float g_tau [2 * B_Q];
__device__ int   g_cnt [2 * B_Q];
__device__ u64   g_f   [(size_t)2 * B_Q * CAP];   // packed (float score, int idx)

// ---------------- helpers ----------------
template <int S>
__device__ __forceinline__ void sinsN(float (&rv)[S], int (&ri)[S], float s, int j) {
    float cv = s; int ci = j;
    #pragma unroll
    for (int k = 0; k < S; k++) {
        bool sm = cv < rv[k];
        float tv = rv[k]; int ti = ri[k];
        rv[k] = sm ? cv : rv[k];
        ri[k] = sm ? ci : ri[k];
        cv = sm ? tv : cv;
        ci = sm ? ti : ci;
    }
}

template <int S>
__device__ __forceinline__ void popN(float (&rv)[S], int (&ri)[S]) {
    #pragma unroll
    for (int k = 0; k < S - 1; k++) { rv[k] = rv[k + 1]; ri[k] = ri[k + 1]; }
    rv[S - 1] = FLT_BIG; ri[S - 1] = 0;
}

__device__ __forceinline__ void wmin(float& v, int& id, int& ln) {
    #pragma unroll
    for (int off = 16; off; off >>= 1) {
        float ov = __shfl_xor_sync(FULLMASK, v,  off);
        int  oid = __shfl_xor_sync(FULLMASK, id, off);
        int  oln = __shfl_xor_sync(FULLMASK, ln, off);
        if (ov < v) { v = ov; id = oid; ln = oln; }
    }
}

__device__ __forceinline__ void load_q_neg2(const float* emb, int self, u64 (&an)[8]) {
    const float4* av = reinterpret_cast<const float4*>(emb) + (size_t)self * 4;
    float4 a0 = av[0], a1 = av[1], a2 = av[2], a3 = av[3];
    PACK2(an[0], -a0.x, -a0.y); PACK2(an[1], -a0.z, -a0.w);
    PACK2(an[2], -a1.x, -a1.y); PACK2(an[3], -a1.z, -a1.w);
    PACK2(an[4], -a2.x, -a2.y); PACK2(an[5], -a2.z, -a2.w);
    PACK2(an[6], -a3.x, -a3.y); PACK2(an[7], -a3.z, -a3.w);
}

// score = 0.5|e|^2 - a.e, acc initialized with packed (0.5|e|^2, 0)
__device__ __forceinline__ float score8(const ulonglong2* __restrict__ e2, const u64 an[8], u64 acc) {
    ulonglong2 u0 = e2[0], u1 = e2[1], u2 = e2[2], u3 = e2[3];
    FMA2(acc, u0.x, an[0], acc); FMA2(acc, u0.y, an[1], acc);
    FMA2(acc, u1.x, an[2], acc); FMA2(acc, u1.y, an[3], acc);
    FMA2(acc, u2.x, an[4], acc); FMA2(acc, u2.y, an[5], acc);
    FMA2(acc, u3.x, an[6], acc); FMA2(acc, u3.y, an[7], acc);
    float lo, hi;
    UNPACK2(lo, hi, acc);
    return lo + hi;
}

// ============ kernel A: per-(pass,query) tau ============
// 64 blocks x 512 threads; block handles 16 (pass,query) pairs; window staged in smem
__global__ __launch_bounds__(512) void prep_kernel(
    const float* __restrict__ emb0, const float* __restrict__ emb1,
    const int* __restrict__ idx0, const int* __restrict__ idx1)
{
    __shared__ float4 smW[128 * 4];   // one 128-candidate tile
    __shared__ u64    smNw[128];      // packed (0.5*norm, 0)

    const int tid  = threadIdx.x;
    const int wid  = tid >> 5;
    const int lane = tid & 31;
    const int w    = blockIdx.x * 16 + wid;   // [0,1024)
    const int pass = w >> 9;                  // uniform per block (16 | 512)
    const int q    = w & (B_Q - 1);

    const float* emb  = pass ? emb1 : emb0;
    const int    self = (pass ? idx1 : idx0)[q];
    const float4* emb4 = reinterpret_cast<const float4*>(emb);

    u64 an[8];
    load_q_neg2(emb, self, an);

    float rv[8]; int ri[8];
    #pragma unroll
    for (int k = 0; k < 8; k++) { rv[k] = FLT_BIG; ri[k] = 0; }

    for (int t = 0; t < WIN / 128; t++) {
        __syncthreads();
        // stage 128 candidates: 512 threads x 1 float4
        {
            int c = tid >> 2, part = tid & 3;
            smW[tid] = emb4[(size_t)(t * 128 + c) * 4 + part];
        }
        __syncthreads();
        // norms
        if (tid < 128) {
            float4 v0 = smW[4*tid], v1 = smW[4*tid+1], v2 = smW[4*tid+2], v3 = smW[4*tid+3];
            float s = v0.x*v0.x + v0.y*v0.y + v0.z*v0.z + v0.w*v0.w
                    + v1.x*v1.x + v1.y*v1.y + v1.z*v1.z + v1.w*v1.w
                    + v2.x*v2.x + v2.y*v2.y + v2.z*v2.z + v2.w*v2.w
                    + v3.x*v3.x + v3.y*v3.y + v3.z*v3.z + v3.w*v3.w;
            u64 pn; PACK2(pn, 0.5f * s, 0.f);
            smNw[tid] = pn;
        }
        __syncthreads();

        const ulonglong2* smW2 = reinterpret_cast<const ulonglong2*>(smW);
        #pragma unroll
        for (int i = 0; i < 4; i++) {
            int c = i * 32 + lane;
            int j = t * 128 + c;
            float s = score8(&smW2[4 * c], an, smNw[c]);
            if (s < rv[7] && j != self) sinsN<8>(rv, ri, s, j);
        }
    }

    // 8th smallest warp-wide
    float tau = 0.f;
    #pragma unroll
    for (int r = 0; r < 8; r++) {
        float v = rv[0]; int id = ri[0]; int ln = lane;
        wmin(v, id, ln);
        if (lane == ln) popN<8>(rv, ri);
        tau = v;
    }

    if (lane == 0) { g_tau[w] = tau; g_cnt[w] = 0; }
}

// ============ kernel B: filter — branch-free survivor push ============
__global__ __launch_bounds__(QPB) void filter_kernel(
    const float* __restrict__ emb0, const float* __restrict__ emb1,
    const int* __restrict__ idx0, const int* __restrict__ idx1)
{
    __shared__ float4 smE[TILE * 4];        // 16KB
    __shared__ u64    smN[TILE];            // 2KB packed (0.5n, 0)
    __shared__ u64    sbuf[BUFD * QPB];     // 24KB, layout [slot][tid]

    const int chunk = blockIdx.x;
    const int qg    = blockIdx.y;
    const int pass  = blockIdx.z;
    const int tid   = threadIdx.x;

    const float* emb = pass ? emb1 : emb0;
    const float4* emb4 = reinterpret_cast<const float4*>(emb);

    const int q    = qg * QPB + tid;
    const int t2   = pass * B_Q + q;
    const int self = (pass ? idx1 : idx0)[q];
    const float tau = g_tau[t2];

    u64 an[8];
    load_q_neg2(emb, self, an);

    const int c0 = chunk * CHUNK;
    const int c1 = min(c0 + CHUNK, N_EMB);

    for (int base = c0; base < c1; base += TILE) {
        __syncthreads();
        // stage 256 candidates (2 per thread), inline half-norm; dummies get FLT_BIG
        for (int c = tid; c < TILE; c += QPB) {
            int gj = base + c;
            if (gj < c1) {
                const float4* gE = emb4 + (size_t)gj * 4;
                float4 v0 = gE[0], v1 = gE[1], v2 = gE[2], v3 = gE[3];
                smE[4*c] = v0; smE[4*c+1] = v1; smE[4*c+2] = v2; smE[4*c+3] = v3;
                float s = v0.x*v0.x + v0.y*v0.y + v0.z*v0.z + v0.w*v0.w
                        + v1.x*v1.x + v1.y*v1.y + v1.z*v1.z + v1.w*v1.w
                        + v2.x*v2.x + v2.y*v2.y + v2.z*v2.z + v2.w*v2.w
                        + v3.x*v3.x + v3.y*v3.y + v3.z*v3.z + v3.w*v3.w;
                u64 pn; PACK2(pn, 0.5f * s, 0.f);
                smN[c] = pn;
            } else {
                float4 z = make_float4(0.f, 0.f, 0.f, 0.f);
                smE[4*c] = z; smE[4*c+1] = z; smE[4*c+2] = z; smE[4*c+3] = z;
                u64 pn; PACK2(pn, FLT_BIG, 0.f);
                smN[c] = pn;
            }
        }
        __syncthreads();

        const ulonglong2* smE2 = reinterpret_cast<const ulonglong2*>(smE);
        int cnt = 0;

        #pragma unroll 1
        for (int cc = 0; cc < TILE; cc += 4) {
            float s0 = score8(&smE2[4*cc],      an, smN[cc]);
            float s1 = score8(&smE2[4*cc + 4],  an, smN[cc + 1]);
            float s2 = score8(&smE2[4*cc + 8],  an, smN[cc + 2]);
            float s3 = score8(&smE2[4*cc + 12], an, smN[cc + 3]);

            // branch-free push: unconditional STS, conditional advance
            u64 v;
            PACKFI(v, s0, base + cc);
            sbuf[min(cnt, BUFD - 1) * QPB + tid] = v;  cnt += (s0 <= tau);
            PACKFI(v, s1, base + cc + 1);
            sbuf[min(cnt, BUFD - 1) * QPB + tid] = v;  cnt += (s1 <= tau);
            PACKFI(v, s2, base + cc + 2);
            sbuf[min(cnt, BUFD - 1) * QPB + tid] = v;  cnt += (s2 <= tau);
            PACKFI(v, s3, base + cc + 3);
            sbuf[min(cnt, BUFD - 1) * QPB + tid] = v;  cnt += (s3 <= tau);
        }

        // flush (once per tile)
        if (cnt > 0) {
            if (cnt > BUFD) cnt = BUFD;
            int slot = atomicAdd(&g_cnt[t2], cnt);
            for (int k = 0; k < cnt; k++) {
                int o = slot + k;
                if (o < CAP) g_f[(size_t)t2 * CAP + o] = sbuf[k * QPB + tid];
            }
        }
    }
}

// ============ kernel C: exact top-20 of survivors + features + fused MLP ============
__global__ __launch_bounds__(128) void select_kernel(
    const float* __restrict__ emb0, const float* __restrict__ emb1,
    const float* __restrict__ rctx0, const float* __restrict__ rctx1,
    const int* __restrict__ idx0, const int* __restrict__ idx1,
    const float* __restrict__ mean_in, const float* __restrict__ std_in,
    const float* __restrict__ W1, const float* __restrict__ b1,
    const float* __restrict__ Wm, const float* __restrict__ bm,
    const float* __restrict__ Ws, const float* __restrict__ bs,
    float* __restrict__ out)
{
    __shared__ float sfe[2][8];

    const int wid  = threadIdx.x >> 5;
    const int lane = threadIdx.x & 31;
    const int ql   = wid >> 1;
    const int pass = wid & 1;
    const int q    = blockIdx.x * 2 + ql;
    const int t2   = pass * B_Q + q;

    const float* rctx = pass ? rctx1 : rctx0;
    const float* emb  = pass ? emb1 : emb0;
    const int    self = (pass ? idx1 : idx0)[q];

    float na;
    {
        const float4* av = reinterpret_cast<const float4*>(emb) + (size_t)self * 4;
        float4 a0 = av[0], a1 = av[1], a2 = av[2], a3 = av[3];
        na = a0.x*a0.x + a0.y*a0.y + a0.z*a0.z + a0.w*a0.w
           + a1.x*a1.x + a1.y*a1.y + a1.z*a1.z + a1.w*a1.w
           + a2.x*a2.x + a2.y*a2.y + a2.z*a2.z + a2.w*a2.w
           + a3.x*a3.x + a3.y*a3.y + a3.z*a3.z + a3.w*a3.w;
    }

    int cnt = g_cnt[t2];
    if (cnt > CAP) cnt = CAP;

    float rv[10]; int ri[10];
    #pragma unroll
    for (int k = 0; k < 10; k++) { rv[k] = FLT_BIG; ri[k] = 0; }
    const u64* GF = g_f + (size_t)t2 * CAP;
    for (int i = lane; i < cnt; i += 32) {
        u64 v = GF[i];
        float s; int j;
        UNPACKFI(s, j, v);
        if (s < rv[9] && j != self) sinsN<10>(rv, ri, s, j);
    }

    float ms = 0.f; int mj = 0;
    #pragma unroll
    for (int r = 0; r < K_NN; r++) {
        float v = rv[0]; int id = ri[0]; int ln = lane;
        wmin(v, id, ln);
        if (lane == ln) popN<10>(rv, ri);
        if (lane == r) { ms = v; mj = id; }
    }

    const bool act = lane < K_NN;
    float w = 0.f, y = 0.f;
    if (act) {
        float d2 = fmaxf(fmaf(2.f, ms, na), 0.f);
        w = expf(-(sqrtf(d2) + 0.001f));
        y = rctx[(size_t)q * N_EMB + mj];
    }
    float f1 = w, f2n = w * y, ysum = y;
    #pragma unroll
    for (int off = 16; off; off >>= 1) {
        f1   += __shfl_xor_sync(FULLMASK, f1,   off);
        f2n  += __shfl_xor_sync(FULLMASK, f2n,  off);
        ysum += __shfl_xor_sync(FULLMASK, ysum, off);
    }
    float mean = ysum * (1.0f / K_NN);
    float d = act ? (y - mean) : 0.f;
    float var = d * d;
    #pragma unroll
    for (int off = 16; off; off >>= 1) var += __shfl_xor_sync(FULLMASK, var, off);
    float f3 = sqrtf(var * (1.0f / (K_NN - 1)));

    if (lane == 0) {
        sfe[ql][pass]     = f1;
        sfe[ql][2 + pass] = f2n / f1;
        sfe[ql][4 + pass] = f3;
        if (pass == 0) {
            sfe[ql][6] = mean_in[q];
            sfe[ql][7] = std_in[q];
        }
    }
    __syncthreads();

    if (wid < 2) {
        const int mq = blockIdx.x * 2 + wid;
        float f[8];
        #pragma unroll
        for (int i = 0; i < 8; i++) f[i] = sfe[wid][i];

        float m = 0.f, sd = 0.f;
        #pragma unroll
        for (int half = 0; half < 2; half++) {
            int j = lane + half * 32;
            float acc = b1[j];
            #pragma unroll
            for (int i = 0; i < 8; i++) acc = fmaf(f[i], W1[i * 64 + j], acc);
            float h = fmaxf(acc, 0.f);
            m  = fmaf(h, Wm[j], m);
            sd = fmaf(h, Ws[j], sd);
        }
        #pragma unroll
        for (int off = 16; off; off >>= 1) {
            m  += __shfl_xor_sync(FULLMASK, m,  off);
            sd += __shfl_xor_sync(FULLMASK, sd, off);
        }
        if (lane == 0) {
            out[mq]       = m  + bm[0];
            out[B_Q + mq] = sd + bs[0];
        }
    }
}

// ---------------- launcher ----------------
extern "C" void kernel_launch(void* const* d_in, const int* in_sizes, int n_in,
                              void* d_out, int out_size)
{
    const float* emb0    = (const float*)d_in[0];
    const float* emb1    = (const float*)d_in[1];
    const float* rctx0   = (const float*)d_in[2];
    const float* rctx1   = (const float*)d_in[3];
    const int*   idx0    = (const int*)d_in[4];
    const int*   idx1    = (const int*)d_in[5];
    const float* mean_in = (const float*)d_in[6];
    const float* std_in  = (const float*)d_in[7];
    const float* W1      = (const float*)d_in[8];
    const float* b1      = (const float*)d_in[9];
    const float* Wm      = (const float*)d_in[10];
    const float* bm      = (const float*)d_in[11];
    const float* Ws      = (const float*)d_in[12];
    const float* bs      = (const float*)d_in[13];
    float* out = (float*)d_out;

    prep_kernel<<<64, 512>>>(emb0, emb1, idx0, idx1);

    dim3 g1(NCHUNK, B_Q / QPB, 2);
    filter_kernel<<<g1, QPB>>>(emb0, emb1, idx0, idx1);

    select_kernel<<<B_Q / 2, 128>>>(emb0, emb1, rctx0, rctx1, idx0, idx1,
                                    mean_in, std_in,
                                    W1, b1, Wm, bm, Ws, bs, out);
}

// round 9
// speedup vs baseline: 5.0053x; 1.0026x over previous
#include <cuda_runtime.h>

// ---------------- problem constants ----------------
#define N_EMB   50000
#define B_Q     512
#define E_DIM   16
#define K_NN    20
#define NCHUNK  64
#define CHUNK   782           // 64*782 = 50048 >= 50000
#define TILE    256
#define QPB     128
#define CAP     1024
#define BUFD    24            // per-thread smem survivor slots per tile
#define WIN     1024          // prep sample window
#define FLT_BIG 3.402823466e+38f
#define FULLMASK 0xffffffffu

typedef unsigned long long u64;

// packed f32x2 helpers
#define FMA2(d, a, b, c) asm("fma.rn.f32x2 %0, %1, %2, %3;" : "=l"(d) : "l"(a), "l"(b), "l"(c))
#define PACK2(d, lo, hi) asm("mov.b64 %0, {%1, %2};" : "=l"(d) : "f"(lo), "f"(hi))
#define UNPACK2(lo, hi, v) asm("mov.b64 {%0, %1}, %2;" : "=f"(lo), "=f"(hi) : "l"(v))
#define PACKFI(d, f, i) asm("mov.b64 %0, {%1, %2};" : "=l"(d) : "f"(f), "r"(i))
#define UNPACKFI(f, i, v) asm("mov.b64 {%0, %1}, %2;" : "=f"(f), "=r"(i) : "l"(v))

// ---------------- scratch ----------------
__device__ float g_tau [2 * B_Q];
__device__ int   g_cnt [2 * B_Q];
__device__ u64   g_f   [(size_t)2 * B_Q * CAP];   // packed (float score, int idx)

// ---------------- helpers ----------------
template <int S>
__device__ __forceinline__ void sinsN(float (&rv)[S], int (&ri)[S], float s, int j) {
    float cv = s; int ci = j;
    #pragma unroll
    for (int k = 0; k < S; k++) {
        bool sm = cv < rv[k];
        float tv = rv[k]; int ti = ri[k];
        rv[k] = sm ? cv : rv[k];
        ri[k] = sm ? ci : ri[k];
        cv = sm ? tv : cv;
        ci = sm ? ti : ci;
    }
}

template <int S>
__device__ __forceinline__ void popN(float (&rv)[S], int (&ri)[S]) {
    #pragma unroll
    for (int k = 0; k < S - 1; k++) { rv[k] = rv[k + 1]; ri[k] = ri[k + 1]; }
    rv[S - 1] = FLT_BIG; ri[S - 1] = 0;
}

__device__ __forceinline__ void wmin(float& v, int& id, int& ln) {
    #pragma unroll
    for (int off = 16; off; off >>= 1) {
        float ov = __shfl_xor_sync(FULLMASK, v,  off);
        int  oid = __shfl_xor_sync(FULLMASK, id, off);
        int  oln = __shfl_xor_sync(FULLMASK, ln, off);
        if (ov < v) { v = ov; id = oid; ln = oln; }
    }
}

__device__ __forceinline__ void load_q_neg2(const float* emb, int self, u64 (&an)[8]) {
    const float4* av = reinterpret_cast<const float4*>(emb) + (size_t)self * 4;
    float4 a0 = av[0], a1 = av[1], a2 = av[2], a3 = av[3];
    PACK2(an[0], -a0.x, -a0.y); PACK2(an[1], -a0.z, -a0.w);
    PACK2(an[2], -a1.x, -a1.y); PACK2(an[3], -a1.z, -a1.w);
    PACK2(an[4], -a2.x, -a2.y); PACK2(an[5], -a2.z, -a2.w);
    PACK2(an[6], -a3.x, -a3.y); PACK2(an[7], -a3.z, -a3.w);
}

// score = 0.5|e|^2 - a.e, acc initialized with packed (0.5|e|^2, 0)
__device__ __forceinline__ float score8(const ulonglong2* __restrict__ e2, const u64 an[8], u64 acc) {
    ulonglong2 u0 = e2[0], u1 = e2[1], u2 = e2[2], u3 = e2[3];
    FMA2(acc, u0.x, an[0], acc); FMA2(acc, u0.y, an[1], acc);
    FMA2(acc, u1.x, an[2], acc); FMA2(acc, u1.y, an[3], acc);
    FMA2(acc, u2.x, an[4], acc); FMA2(acc, u2.y, an[5], acc);
    FMA2(acc, u3.x, an[6], acc); FMA2(acc, u3.y, an[7], acc);
    float lo, hi;
    UNPACK2(lo, hi, acc);
    return lo + hi;
}

// ============ kernel A: per-(pass,query) tau ============
// 64 blocks x 512 threads; block handles 16 (pass,query) pairs; window staged in smem
__global__ __launch_bounds__(512) void prep_kernel(
    const float* __restrict__ emb0, const float* __restrict__ emb1,
    const int* __restrict__ idx0, const int* __restrict__ idx1)
{
    __shared__ float4 smW[128 * 4];   // one 128-candidate tile
    __shared__ u64    smNw[128];      // packed (0.5*norm, 0)

    const int tid  = threadIdx.x;
    const int wid  = tid >> 5;
    const int lane = tid & 31;
    const int w    = blockIdx.x * 16 + wid;   // [0,1024)
    const int pass = w >> 9;                  // uniform per block (16 | 512)
    const int q    = w & (B_Q - 1);

    const float* emb  = pass ? emb1 : emb0;
    const int    self = (pass ? idx1 : idx0)[q];
    const float4* emb4 = reinterpret_cast<const float4*>(emb);

    u64 an[8];
    load_q_neg2(emb, self, an);

    float rv[8]; int ri[8];
    #pragma unroll
    for (int k = 0; k < 8; k++) { rv[k] = FLT_BIG; ri[k] = 0; }

    for (int t = 0; t < WIN / 128; t++) {
        __syncthreads();
        // stage 128 candidates: 512 threads x 1 float4
        {
            int c = tid >> 2, part = tid & 3;
            smW[tid] = emb4[(size_t)(t * 128 + c) * 4 + part];
        }
        __syncthreads();
        // norms
        if (tid < 128) {
            float4 v0 = smW[4*tid], v1 = smW[4*tid+1], v2 = smW[4*tid+2], v3 = smW[4*tid+3];
            float s = v0.x*v0.x + v0.y*v0.y + v0.z*v0.z + v0.w*v0.w
                    + v1.x*v1.x + v1.y*v1.y + v1.z*v1.z + v1.w*v1.w
                    + v2.x*v2.x + v2.y*v2.y + v2.z*v2.z + v2.w*v2.w
                    + v3.x*v3.x + v3.y*v3.y + v3.z*v3.z + v3.w*v3.w;
            u64 pn; PACK2(pn, 0.5f * s, 0.f);
            smNw[tid] = pn;
        }
        __syncthreads();

        const ulonglong2* smW2 = reinterpret_cast<const ulonglong2*>(smW);
        #pragma unroll
        for (int i = 0; i < 4; i++) {
            int c = i * 32 + lane;
            int j = t * 128 + c;
            float s = score8(&smW2[4 * c], an, smNw[c]);
            if (s < rv[7] && j != self) sinsN<8>(rv, ri, s, j);
        }
    }

    // 8th smallest warp-wide
    float tau = 0.f;
    #pragma unroll
    for (int r = 0; r < 8; r++) {
        float v = rv[0]; int id = ri[0]; int ln = lane;
        wmin(v, id, ln);
        if (lane == ln) popN<8>(rv, ri);
        tau = v;
    }

    if (lane == 0) { g_tau[w] = tau; g_cnt[w] = 0; }
}

// ============ kernel B: filter — branch-free survivor push ============
__global__ __launch_bounds__(QPB) void filter_kernel(
    const float* __restrict__ emb0, const float* __restrict__ emb1,
    const int* __restrict__ idx0, const int* __restrict__ idx1)
{
    __shared__ float4 smE[TILE * 4];        // 16KB
    __shared__ u64    smN[TILE];            // 2KB packed (0.5n, 0)
    __shared__ u64    sbuf[BUFD * QPB];     // 24KB, layout [slot][tid]

    const int chunk = blockIdx.x;
    const int qg    = blockIdx.y;
    const int pass  = blockIdx.z;
    const int tid   = threadIdx.x;

    const float* emb = pass ? emb1 : emb0;
    const float4* emb4 = reinterpret_cast<const float4*>(emb);

    const int q    = qg * QPB + tid;
    const int t2   = pass * B_Q + q;
    const int self = (pass ? idx1 : idx0)[q];
    const float tau = g_tau[t2];

    u64 an[8];
    load_q_neg2(emb, self, an);

    const int c0 = chunk * CHUNK;
    const int c1 = min(c0 + CHUNK, N_EMB);

    for (int base = c0; base < c1; base += TILE) {
        __syncthreads();
        // stage 256 candidates (2 per thread), inline half-norm; dummies get FLT_BIG
        for (int c = tid; c < TILE; c += QPB) {
            int gj = base + c;
            if (gj < c1) {
                const float4* gE = emb4 + (size_t)gj * 4;
                float4 v0 = gE[0], v1 = gE[1], v2 = gE[2], v3 = gE[3];
                smE[4*c] = v0; smE[4*c+1] = v1; smE[4*c+2] = v2; smE[4*c+3] = v3;
                float s = v0.x*v0.x + v0.y*v0.y + v0.z*v0.z + v0.w*v0.w
                        + v1.x*v1.x + v1.y*v1.y + v1.z*v1.z + v1.w*v1.w
                        + v2.x*v2.x + v2.y*v2.y + v2.z*v2.z + v2.w*v2.w
                        + v3.x*v3.x + v3.y*v3.y + v3.z*v3.z + v3.w*v3.w;
                u64 pn; PACK2(pn, 0.5f * s, 0.f);
                smN[c] = pn;
            } else {
                float4 z = make_float4(0.f, 0.f, 0.f, 0.f);
                smE[4*c] = z; smE[4*c+1] = z; smE[4*c+2] = z; smE[4*c+3] = z;
                u64 pn; PACK2(pn, FLT_BIG, 0.f);
                smN[c] = pn;
            }
        }
        __syncthreads();

        const ulonglong2* smE2 = reinterpret_cast<const ulonglong2*>(smE);
        int cnt = 0;

        #pragma unroll 1
        for (int cc = 0; cc < TILE; cc += 4) {
            float s0 = score8(&smE2[4*cc],      an, smN[cc]);
            float s1 = score8(&smE2[4*cc + 4],  an, smN[cc + 1]);
            float s2 = score8(&smE2[4*cc + 8],  an, smN[cc + 2]);
            float s3 = score8(&smE2[4*cc + 12], an, smN[cc + 3]);

            // branch-free push: unconditional STS, conditional advance
            u64 v;
            PACKFI(v, s0, base + cc);
            sbuf[min(cnt, BUFD - 1) * QPB + tid] = v;  cnt += (s0 <= tau);
            PACKFI(v, s1, base + cc + 1);
            sbuf[min(cnt, BUFD - 1) * QPB + tid] = v;  cnt += (s1 <= tau);
            PACKFI(v, s2, base + cc + 2);
            sbuf[min(cnt, BUFD - 1) * QPB + tid] = v;  cnt += (s2 <= tau);
            PACKFI(v, s3, base + cc + 3);
            sbuf[min(cnt, BUFD - 1) * QPB + tid] = v;  cnt += (s3 <= tau);
        }

        // flush (once per tile)
        if (cnt > 0) {
            if (cnt > BUFD) cnt = BUFD;
            int slot = atomicAdd(&g_cnt[t2], cnt);
            for (int k = 0; k < cnt; k++) {
                int o = slot + k;
                if (o < CAP) g_f[(size_t)t2 * CAP + o] = sbuf[k * QPB + tid];
            }
        }
    }
}

// ============ kernel C: exact top-20 of survivors + features + fused MLP ============
__global__ __launch_bounds__(128) void select_kernel(
    const float* __restrict__ emb0, const float* __restrict__ emb1,
    const float* __restrict__ rctx0, const float* __restrict__ rctx1,
    const int* __restrict__ idx0, const int* __restrict__ idx1,
    const float* __restrict__ mean_in, const float* __restrict__ std_in,
    const float* __restrict__ W1, const float* __restrict__ b1,
    const float* __restrict__ Wm, const float* __restrict__ bm,
    const float* __restrict__ Ws, const float* __restrict__ bs,
    float* __restrict__ out)
{
    __shared__ float sfe[2][8];

    const int wid  = threadIdx.x >> 5;
    const int lane = threadIdx.x & 31;
    const int ql   = wid >> 1;
    const int pass = wid & 1;
    const int q    = blockIdx.x * 2 + ql;
    const int t2   = pass * B_Q + q;

    const float* rctx = pass ? rctx1 : rctx0;
    const float* emb  = pass ? emb1 : emb0;
    const int    self = (pass ? idx1 : idx0)[q];

    float na;
    {
        const float4* av = reinterpret_cast<const float4*>(emb) + (size_t)self * 4;
        float4 a0 = av[0], a1 = av[1], a2 = av[2], a3 = av[3];
        na = a0.x*a0.x + a0.y*a0.y + a0.z*a0.z + a0.w*a0.w
           + a1.x*a1.x + a1.y*a1.y + a1.z*a1.z + a1.w*a1.w
           + a2.x*a2.x + a2.y*a2.y + a2.z*a2.z + a2.w*a2.w
           + a3.x*a3.x + a3.y*a3.y + a3.z*a3.z + a3.w*a3.w;
    }

    int cnt = g_cnt[t2];
    if (cnt > CAP) cnt = CAP;

    float rv[10]; int ri[10];
    #pragma unroll
    for (int k = 0; k < 10; k++) { rv[k] = FLT_BIG; ri[k] = 0; }
    const u64* GF = g_f + (size_t)t2 * CAP;
    for (int i = lane; i < cnt; i += 32) {
        u64 v = GF[i];
        float s; int j;
        UNPACKFI(s, j, v);
        if (s < rv[9] && j != self) sinsN<10>(rv, ri, s, j);
    }

    float ms = 0.f; int mj = 0;
    #pragma unroll
    for (int r = 0; r < K_NN; r++) {
        float v = rv[0]; int id = ri[0]; int ln = lane;
        wmin(v, id, ln);
        if (lane == ln) popN<10>(rv, ri);
        if (lane == r) { ms = v; mj = id; }
    }

    const bool act = lane < K_NN;
    float w = 0.f, y = 0.f;
    if (act) {
        float d2 = fmaxf(fmaf(2.f, ms, na), 0.f);
        w = expf(-(sqrtf(d2) + 0.001f));
        y = rctx[(size_t)q * N_EMB + mj];
    }
    float f1 = w, f2n = w * y, ysum = y;
    #pragma unroll
    for (int off = 16; off; off >>= 1) {
        f1   += __shfl_xor_sync(FULLMASK, f1,   off);
        f2n  += __shfl_xor_sync(FULLMASK, f2n,  off);
        ysum += __shfl_xor_sync(FULLMASK, ysum, off);
    }
    float mean = ysum * (1.0f / K_NN);
    float d = act ? (y - mean) : 0.f;
    float var = d * d;
    #pragma unroll
    for (int off = 16; off; off >>= 1) var += __shfl_xor_sync(FULLMASK, var, off);
    float f3 = sqrtf(var * (1.0f / (K_NN - 1)));

    if (lane == 0) {
        sfe[ql][pass]     = f1;
        sfe[ql][2 + pass] = f2n / f1;
        sfe[ql][4 + pass] = f3;
        if (pass == 0) {
            sfe[ql][6] = mean_in[q];
            sfe[ql][7] = std_in[q];
        }
    }
    __syncthreads();

    if (wid < 2) {
        const int mq = blockIdx.x * 2 + wid;
        float f[8];
        #pragma unroll
        for (int i = 0; i < 8; i++) f[i] = sfe[wid][i];

        float m = 0.f, sd = 0.f;
        #pragma unroll
        for (int half = 0; half < 2; half++) {
            int j = lane + half * 32;
            float acc = b1[j];
            #pragma unroll
            for (int i = 0; i < 8; i++) acc = fmaf(f[i], W1[i * 64 + j], acc);
            float h = fmaxf(acc, 0.f);
            m  = fmaf(h, Wm[j], m);
            sd = fmaf(h, Ws[j], sd);
        }
        #pragma unroll
        for (int off = 16; off; off >>= 1) {
            m  += __shfl_xor_sync(FULLMASK, m,  off);
            sd += __shfl_xor_sync(FULLMASK, sd, off);
        }
        if (lane == 0) {
            out[mq]       = m  + bm[0];
            out[B_Q + mq] = sd + bs[0];
        }
    }
}

// ---------------- launcher ----------------
extern "C" void kernel_launch(void* const* d_in, const int* in_sizes, int n_in,
                              void* d_out, int out_size)
{
    const float* emb0    = (const float*)d_in[0];
    const float* emb1    = (const float*)d_in[1];
    const float* rctx0   = (const float*)d_in[2];
    const float* rctx1   = (const float*)d_in[3];
    const int*   idx0    = (const int*)d_in[4];
    const int*   idx1    = (const int*)d_in[5];
    const float* mean_in = (const float*)d_in[6];
    const float* std_in  = (const float*)d_in[7];
    const float* W1      = (const float*)d_in[8];
    const float* b1      = (const float*)d_in[9];
    const float* Wm      = (const float*)d_in[10];
    const float* bm      = (const float*)d_in[11];
    const float* Ws      = (const float*)d_in[12];
    const float* bs      = (const float*)d_in[13];
    float* out = (float*)d_out;

    prep_kernel<<<64, 512>>>(emb0, emb1, idx0, idx1);

    dim3 g1(NCHUNK, B_Q / QPB, 2);
    filter_kernel<<<g1, QPB>>>(emb0, emb1, idx0, idx1);

    select_kernel<<<B_Q / 2, 128>>>(emb0, emb1, rctx0, rctx1, idx0, idx1,
                                    mean_in, std_in,
                                    W1, b1, Wm, bm, Ws, bs, out);
}

// round 10
// speedup vs baseline: 5.4809x; 1.0950x over previous
#include <cuda_runtime.h>

// ---------------- problem constants ----------------
#define N_EMB   50000
#define B_Q     512
#define E_DIM   16
#define K_NN    20
#define NCHUNK  64
#define CHUNK   782           // 64*782 = 50048 >= 50000
#define TILE    256
#define QPB     128
#define CAP     2048
#define BUFD    16            // per-thread smem survivor slots per tile
#define WIN     1024          // prep sample window
#define FLT_BIG 3.402823466e+38f
#define FULLMASK 0xffffffffu

typedef unsigned long long u64;

// packed f32x2 helpers
#define FMA2(d, a, b, c) asm("fma.rn.f32x2 %0, %1, %2, %3;" : "=l"(d) : "l"(a), "l"(b), "l"(c))
#define PACK2(d, lo, hi) asm("mov.b64 %0, {%1, %2};" : "=l"(d) : "f"(lo), "f"(hi))
#define UNPACK2(lo, hi, v) asm("mov.b64 {%0, %1}, %2;" : "=f"(lo), "=f"(hi) : "l"(v))
#define PACKFI(d, f, i) asm("mov.b64 %0, {%1, %2};" : "=l"(d) : "f"(f), "r"(i))
#define UNPACKFI(f, i, v) asm("mov.b64 {%0, %1}, %2;" : "=f"(f), "=r"(i) : "l"(v))

// ---------------- scratch ----------------
__device__ float g_tau [2 * B_Q];
__device__ int   g_cnt [2 * B_Q];
__device__ u64   g_f   [(size_t)2 * B_Q * CAP];   // packed (float score, int idx)

// ---------------- helpers ----------------
template <int S>
__device__ __forceinline__ void sinsN(float (&rv)[S], int (&ri)[S], float s, int j) {
    float cv = s; int ci = j;
    #pragma unroll
    for (int k = 0; k < S; k++) {
        bool sm = cv < rv[k];
        float tv = rv[k]; int ti = ri[k];
        rv[k] = sm ? cv : rv[k];
        ri[k] = sm ? ci : ri[k];
        cv = sm ? tv : cv;
        ci = sm ? ti : ci;
    }
}

template <int S>
__device__ __forceinline__ void popN(float (&rv)[S], int (&ri)[S]) {
    #pragma unroll
    for (int k = 0; k < S - 1; k++) { rv[k] = rv[k + 1]; ri[k] = ri[k + 1]; }
    rv[S - 1] = FLT_BIG; ri[S - 1] = 0;
}

__device__ __forceinline__ void wmin(float& v, int& id, int& ln) {
    #pragma unroll
    for (int off = 16; off; off >>= 1) {
        float ov = __shfl_xor_sync(FULLMASK, v,  off);
        int  oid = __shfl_xor_sync(FULLMASK, id, off);
        int  oln = __shfl_xor_sync(FULLMASK, ln, off);
        if (ov < v) { v = ov; id = oid; ln = oln; }
    }
}

__device__ __forceinline__ void wminv(float& v) {
    #pragma unroll
    for (int off = 16; off; off >>= 1) {
        float ov = __shfl_xor_sync(FULLMASK, v, off);
        v = (ov < v) ? ov : v;
    }
}

__device__ __forceinline__ void load_q_neg2(const float* emb, int self, u64 (&an)[8]) {
    const float4* av = reinterpret_cast<const float4*>(emb) + (size_t)self * 4;
    float4 a0 = av[0], a1 = av[1], a2 = av[2], a3 = av[3];
    PACK2(an[0], -a0.x, -a0.y); PACK2(an[1], -a0.z, -a0.w);
    PACK2(an[2], -a1.x, -a1.y); PACK2(an[3], -a1.z, -a1.w);
    PACK2(an[4], -a2.x, -a2.y); PACK2(an[5], -a2.z, -a2.w);
    PACK2(an[6], -a3.x, -a3.y); PACK2(an[7], -a3.z, -a3.w);
}

// score = 0.5|e|^2 - a.e with acc pre-init (0.5n, 0); TWO accumulator chains
__device__ __forceinline__ float score8(const ulonglong2* __restrict__ e2, const u64 an[8], u64 acc0) {
    ulonglong2 u0 = e2[0], u1 = e2[1], u2 = e2[2], u3 = e2[3];
    u64 acc1 = 0ull;
    FMA2(acc0, u0.x, an[0], acc0); FMA2(acc1, u0.y, an[1], acc1);
    FMA2(acc0, u1.x, an[2], acc0); FMA2(acc1, u1.y, an[3], acc1);
    FMA2(acc0, u2.x, an[4], acc0); FMA2(acc1, u2.y, an[5], acc1);
    FMA2(acc0, u3.x, an[6], acc0); FMA2(acc1, u3.y, an[7], acc1);
    float l0, h0, l1, h1;
    UNPACK2(l0, h0, acc0);
    UNPACK2(l1, h1, acc1);
    return (l0 + h0) + (l1 + h1);
}

// ============ kernel A: per-(pass,query) tau — block per query, 4 warps split window ============
__global__ __launch_bounds__(128) void prep_kernel(
    const float* __restrict__ emb0, const float* __restrict__ emb1,
    const int* __restrict__ idx0, const int* __restrict__ idx1)
{
    __shared__ float sv[32];

    const int tid  = threadIdx.x;
    const int wid  = tid >> 5;
    const int lane = tid & 31;
    const int w    = blockIdx.x;            // [0,1024)
    const int pass = w >> 9;
    const int q    = w & (B_Q - 1);

    const float* emb  = pass ? emb1 : emb0;
    const int    self = (pass ? idx1 : idx0)[q];

    u64 an[8];
    load_q_neg2(emb, self, an);
    u64 halfp;
    PACK2(halfp, 0.5f, 0.5f);

    float rv[8]; int ri[8];
    #pragma unroll
    for (int k = 0; k < 8; k++) { rv[k] = FLT_BIG; ri[k] = 0; }

    const ulonglong2* emb2 = reinterpret_cast<const ulonglong2*>(emb);

    // this warp scans window quarter [wid*256, wid*256+256)
    #pragma unroll 2
    for (int i = 0; i < 8; i++) {
        int j = wid * 256 + i * 32 + lane;
        const ulonglong2* p = emb2 + (size_t)j * 4;
        ulonglong2 u0 = p[0], u1 = p[1], u2 = p[2], u3 = p[3];
        // s = sum e*(0.5e - a): h = fma(e, 0.5, -a); acc = fma(e, h, 0)
        u64 h0, h1, h2, h3, h4, h5, h6, h7;
        FMA2(h0, u0.x, halfp, an[0]); FMA2(h1, u0.y, halfp, an[1]);
        FMA2(h2, u1.x, halfp, an[2]); FMA2(h3, u1.y, halfp, an[3]);
        FMA2(h4, u2.x, halfp, an[4]); FMA2(h5, u2.y, halfp, an[5]);
        FMA2(h6, u3.x, halfp, an[6]); FMA2(h7, u3.y, halfp, an[7]);
        u64 acc0 = 0ull, acc1 = 0ull;
        FMA2(acc0, u0.x, h0, acc0); FMA2(acc1, u0.y, h1, acc1);
        FMA2(acc0, u1.x, h2, acc0); FMA2(acc1, u1.y, h3, acc1);
        FMA2(acc0, u2.x, h4, acc0); FMA2(acc1, u2.y, h5, acc1);
        FMA2(acc0, u3.x, h6, acc0); FMA2(acc1, u3.y, h7, acc1);
        float l0, hh0, l1, hh1;
        UNPACK2(l0, hh0, acc0);
        UNPACK2(l1, hh1, acc1);
        float s = (l0 + hh0) + (l1 + hh1);
        if (s < rv[7] && j != self) sinsN<8>(rv, ri, s, j);
    }

    // per-warp 8 smallest (values only) -> smem[wid*8 + r]
    #pragma unroll
    for (int r = 0; r < 8; r++) {
        float v = rv[0]; int id = ri[0]; int ln = lane;
        wmin(v, id, ln);
        if (lane == ln) popN<8>(rv, ri);
        if (lane == 0) sv[wid * 8 + r] = v;
    }
    __syncthreads();

    // warp 0 merges 32 values -> 8th smallest
    if (wid == 0) {
        float v = sv[lane];
        // extract min 8 times; invalidate the winner each round
        float tau = 0.f;
        #pragma unroll
        for (int r = 0; r < 8; r++) {
            float mv = v;
            wminv(mv);
            tau = mv;
            if (v == mv) v = FLT_BIG;   // ties both removed: conservative (tau only shrinks... )
        }
        if (lane == 0) { g_tau[w] = tau; g_cnt[w] = 0; }
    }
}

// ============ kernel B: filter — branch-free survivor push ============
__global__ __launch_bounds__(QPB) void filter_kernel(
    const float* __restrict__ emb0, const float* __restrict__ emb1,
    const int* __restrict__ idx0, const int* __restrict__ idx1)
{
    __shared__ float4 smE[TILE * 4];        // 16KB
    __shared__ u64    smN[TILE];            // 2KB packed (0.5n, 0)
    __shared__ u64    sbuf[BUFD * QPB];     // 16KB, layout [slot][tid]

    const int chunk = blockIdx.x;
    const int qg    = blockIdx.y;
    const int pass  = blockIdx.z;
    const int tid   = threadIdx.x;

    const float* emb = pass ? emb1 : emb0;
    const float4* emb4 = reinterpret_cast<const float4*>(emb);

    const int q    = qg * QPB + tid;
    const int t2   = pass * B_Q + q;
    const int self = (pass ? idx1 : idx0)[q];
    const float tau = g_tau[t2];

    u64 an[8];
    load_q_neg2(emb, self, an);

    const int c0 = chunk * CHUNK;
    const int c1 = min(c0 + CHUNK, N_EMB);

    for (int base = c0; base < c1; base += TILE) {
        __syncthreads();
        for (int c = tid; c < TILE; c += QPB) {
            int gj = base + c;
            if (gj < c1) {
                const float4* gE = emb4 + (size_t)gj * 4;
                float4 v0 = gE[0], v1 = gE[1], v2 = gE[2], v3 = gE[3];
                smE[4*c] = v0; smE[4*c+1] = v1; smE[4*c+2] = v2; smE[4*c+3] = v3;
                float s = v0.x*v0.x + v0.y*v0.y + v0.z*v0.z + v0.w*v0.w
                        + v1.x*v1.x + v1.y*v1.y + v1.z*v1.z + v1.w*v1.w
                        + v2.x*v2.x + v2.y*v2.y + v2.z*v2.z + v2.w*v2.w
                        + v3.x*v3.x + v3.y*v3.y + v3.z*v3.z + v3.w*v3.w;
                u64 pn; PACK2(pn, 0.5f * s, 0.f);
                smN[c] = pn;
            } else {
                float4 z = make_float4(0.f, 0.f, 0.f, 0.f);
                smE[4*c] = z; smE[4*c+1] = z; smE[4*c+2] = z; smE[4*c+3] = z;
                u64 pn; PACK2(pn, FLT_BIG, 0.f);
                smN[c] = pn;
            }
        }
        __syncthreads();

        const ulonglong2* smE2 = reinterpret_cast<const ulonglong2*>(smE);
        int cnt = 0;

        #pragma unroll 1
        for (int cc = 0; cc < TILE; cc += 4) {
            float s0 = score8(&smE2[4*cc],      an, smN[cc]);
            float s1 = score8(&smE2[4*cc + 4],  an, smN[cc + 1]);
            float s2 = score8(&smE2[4*cc + 8],  an, smN[cc + 2]);
            float s3 = score8(&smE2[4*cc + 12], an, smN[cc + 3]);

            u64 v;
            PACKFI(v, s0, base + cc);
            sbuf[min(cnt, BUFD - 1) * QPB + tid] = v;  cnt += (s0 <= tau);
            PACKFI(v, s1, base + cc + 1);
            sbuf[min(cnt, BUFD - 1) * QPB + tid] = v;  cnt += (s1 <= tau);
            PACKFI(v, s2, base + cc + 2);
            sbuf[min(cnt, BUFD - 1) * QPB + tid] = v;  cnt += (s2 <= tau);
            PACKFI(v, s3, base + cc + 3);
            sbuf[min(cnt, BUFD - 1) * QPB + tid] = v;  cnt += (s3 <= tau);
        }

        if (cnt > 0) {
            if (cnt > BUFD) cnt = BUFD;
            int slot = atomicAdd(&g_cnt[t2], cnt);
            for (int k = 0; k < cnt; k++) {
                int o = slot + k;
                if (o < CAP) g_f[(size_t)t2 * CAP + o] = sbuf[k * QPB + tid];
            }
        }
    }
}

// ============ kernel C: exact top-20 of survivors + features + fused MLP ============
__global__ __launch_bounds__(128) void select_kernel(
    const float* __restrict__ emb0, const float* __restrict__ emb1,
    const float* __restrict__ rctx0, const float* __restrict__ rctx1,
    const int* __restrict__ idx0, const int* __restrict__ idx1,
    const float* __restrict__ mean_in, const float* __restrict__ std_in,
    const float* __restrict__ W1, const float* __restrict__ b1,
    const float* __restrict__ Wm, const float* __restrict__ bm,
    const float* __restrict__ Ws, const float* __restrict__ bs,
    float* __restrict__ out)
{
    __shared__ float sfe[2][8];

    const int wid  = threadIdx.x >> 5;
    const int lane = threadIdx.x & 31;
    const int ql   = wid >> 1;
    const int pass = wid & 1;
    const int q    = blockIdx.x * 2 + ql;
    const int t2   = pass * B_Q + q;

    const float* rctx = pass ? rctx1 : rctx0;
    const float* emb  = pass ? emb1 : emb0;
    const int    self = (pass ? idx1 : idx0)[q];

    float na;
    {
        const float4* av = reinterpret_cast<const float4*>(emb) + (size_t)self * 4;
        float4 a0 = av[0], a1 = av[1], a2 = av[2], a3 = av[3];
        na = a0.x*a0.x + a0.y*a0.y + a0.z*a0.z + a0.w*a0.w
           + a1.x*a1.x + a1.y*a1.y + a1.z*a1.z + a1.w*a1.w
           + a2.x*a2.x + a2.y*a2.y + a2.z*a2.z + a2.w*a2.w
           + a3.x*a3.x + a3.y*a3.y + a3.z*a3.z + a3.w*a3.w;
    }

    int cnt = g_cnt[t2];
    if (cnt > CAP) cnt = CAP;

    float rv[10]; int ri[10];
    #pragma unroll
    for (int k = 0; k < 10; k++) { rv[k] = FLT_BIG; ri[k] = 0; }
    const u64* GF = g_f + (size_t)t2 * CAP;
    for (int i = lane; i < cnt; i += 32) {
        u64 v = GF[i];
        float s; int j;
        UNPACKFI(s, j, v);
        if (s < rv[9] && j != self) sinsN<10>(rv, ri, s, j);
    }

    float ms = 0.f; int mj = 0;
    #pragma unroll
    for (int r = 0; r < K_NN; r++) {
        float v = rv[0]; int id = ri[0]; int ln = lane;
        wmin(v, id, ln);
        if (lane == ln) popN<10>(rv, ri);
        if (lane == r) { ms = v; mj = id; }
    }

    const bool act = lane < K_NN;
    float w = 0.f, y = 0.f;
    if (act) {
        float d2 = fmaxf(fmaf(2.f, ms, na), 0.f);
        w = expf(-(sqrtf(d2) + 0.001f));
        y = rctx[(size_t)q * N_EMB + mj];
    }
    float f1 = w, f2n = w * y, ysum = y;
    #pragma unroll
    for (int off = 16; off; off >>= 1) {
        f1   += __shfl_xor_sync(FULLMASK, f1,   off);
        f2n  += __shfl_xor_sync(FULLMASK, f2n,  off);
        ysum += __shfl_xor_sync(FULLMASK, ysum, off);
    }
    float mean = ysum * (1.0f / K_NN);
    float d = act ? (y - mean) : 0.f;
    float var = d * d;
    #pragma unroll
    for (int off = 16; off; off >>= 1) var += __shfl_xor_sync(FULLMASK, var, off);
    float f3 = sqrtf(var * (1.0f / (K_NN - 1)));

    if (lane == 0) {
        sfe[ql][pass]     = f1;
        sfe[ql][2 + pass] = f2n / f1;
        sfe[ql][4 + pass] = f3;
        if (pass == 0) {
            sfe[ql][6] = mean_in[q];
            sfe[ql][7] = std_in[q];
        }
    }
    __syncthreads();

    if (wid < 2) {
        const int mq = blockIdx.x * 2 + wid;
        float f[8];
        #pragma unroll
        for (int i = 0; i < 8; i++) f[i] = sfe[wid][i];

        float m = 0.f, sd = 0.f;
        #pragma unroll
        for (int half = 0; half < 2; half++) {
            int j = lane + half * 32;
            float acc = b1[j];
            #pragma unroll
            for (int i = 0; i < 8; i++) acc = fmaf(f[i], W1[i * 64 + j], acc);
            float h = fmaxf(acc, 0.f);
            m  = fmaf(h, Wm[j], m);
            sd = fmaf(h, Ws[j], sd);
        }
        #pragma unroll
        for (int off = 16; off; off >>= 1) {
            m  += __shfl_xor_sync(FULLMASK, m,  off);
            sd += __shfl_xor_sync(FULLMASK, sd, off);
        }
        if (lane == 0) {
            out[mq]       = m  + bm[0];
            out[B_Q + mq] = sd + bs[0];
        }
    }
}

// ---------------- launcher ----------------
extern "C" void kernel_launch(void* const* d_in, const int* in_sizes, int n_in,
                              void* d_out, int out_size)
{
    const float* emb0    = (const float*)d_in[0];
    const float* emb1    = (const float*)d_in[1];
    const float* rctx0   = (const float*)d_in[2];
    const float* rctx1   = (const float*)d_in[3];
    const int*   idx0    = (const int*)d_in[4];
    const int*   idx1    = (const int*)d_in[5];
    const float* mean_in = (const float*)d_in[6];
    const float* std_in  = (const float*)d_in[7];
    const float* W1      = (const float*)d_in[8];
    const float* b1      = (const float*)d_in[9];
    const float* Wm      = (const float*)d_in[10];
    const float* bm      = (const float*)d_in[11];
    const float* Ws      = (const float*)d_in[12];
    const float* bs      = (const float*)d_in[13];
    float* out = (float*)d_out;

    prep_kernel<<<2 * B_Q, 128>>>(emb0, emb1, idx0, idx1);

    dim3 g1(NCHUNK, B_Q / QPB, 2);
    filter_kernel<<<g1, QPB>>>(emb0, emb1, idx0, idx1);

    select_kernel<<<B_Q / 2, 128>>>(emb0, emb1, rctx0, rctx1, idx0, idx1,
                                    mean_in, std_in,
                                    W1, b1, Wm, bm, Ws, bs, out);
}